// round 4
// baseline (speedup 1.0000x reference)
#include <cuda_runtime.h>
#include <cstdint>
#include <cstddef>

// Packed fp32x2 helpers (sm_100+ PTX; ptxas never auto-generates FFMA2)
#define FMA2(d, a, b) asm("fma.rn.f32x2 %0, %1, %2, %0;" : "+l"(d) : "l"(a), "l"(b))
#define PACK2(d, f)   asm("mov.b64 %0, {%1, %1};" : "=l"(d) : "f"(f))
#define UNPK2(lo, hi, v) asm("mov.b64 {%0, %1}, %2;" : "=f"(lo), "=f"(hi) : "l"(v))

namespace cfg {
constexpr int T  = 128;   // tokens
constexpr int E  = 256;   // embed
constexpr int H  = 64;    // head dim
constexpr int N3 = 192;   // H * 3 (Q|K|V concat)
constexpr int QKV_STRIDE = 196;  // padded row stride (floats) to break bank conflicts
constexpr int S_STRIDE   = 129;  // padded score row stride
constexpr int XS_FLOATS  = T * E;                 // 32768
constexpr int WBUF_OFF   = XS_FLOATS;             // Wbuf after Xs
constexpr int WBUF_FLOATS = 2 * 32 * N3;          // 12288 (double buffer of 32x192)
constexpr int S_OFF   = T * QKV_STRIDE;           // 25088  (QKV occupies [0, 25088) floats)
constexpr int RED_OFF = S_OFF + T * S_STRIDE;     // 41600
constexpr int SMEM_FLOATS = XS_FLOATS + WBUF_FLOATS;  // 45056
constexpr int SMEM_BYTES  = SMEM_FLOATS * 4;          // 180224 (<= 227KB dyn smem limit)
}

__global__ __launch_bounds__(256, 1)
void attn_head_kernel(const float* __restrict__ x,
                      const float* __restrict__ Wq,
                      const float* __restrict__ Wk,
                      const float* __restrict__ Wv,
                      float* __restrict__ out)
{
    using namespace cfg;
    extern __shared__ float sm[];
    const int tid = threadIdx.x;
    const int b   = blockIdx.x;

    float* Xs   = sm;
    float* Wbuf = sm + WBUF_OFF;

    // ---------------- Phase 0: stage x_b into smem (coalesced f4 copy) ----------------
    {
        const float4* xb = (const float4*)(x + (size_t)b * (T * E));
        float4*       xd = (float4*)Xs;
        #pragma unroll
        for (int i = 0; i < 32; ++i)
            xd[i * 256 + tid] = xb[i * 256 + tid];
    }

    // Per-thread W-gather sources (Q|K|V interleaved into [32 x 192] chunks).
    // float4 index q = i*256+tid over a 32x192 chunk: kk = q/48, col = (q%48)*4.
    const float* wsrc[6];
    {
        #pragma unroll
        for (int i = 0; i < 6; ++i) {
            int q   = i * 256 + tid;
            int kk  = q / 48;
            int c4  = q - kk * 48;
            int col = c4 * 4;
            const float* base = (col < 64)  ? (Wq + col)
                              : (col < 128) ? (Wk + col - 64)
                                            : (Wv + col - 128);
            wsrc[i] = base + kk * H;   // add (krow_chunk)*2048 per chunk later
        }
    }
    // Load W chunk 0 into buffer 0
    {
        float4* wd = (float4*)Wbuf;
        #pragma unroll
        for (int i = 0; i < 6; ++i)
            wd[i * 256 + tid] = *(const float4*)(wsrc[i]);
    }
    __syncthreads();

    // ---------------- Phase 1: QKV = x_b @ [Wq|Wk|Wv]  (M=128,N=192,K=256) ----------------
    const int tx = tid & 15;    // col group: cols 2*tx + 32*p, p<6
    const int ty = tid >> 4;    // row group: rows ty + 16*r,  r<8

    unsigned long long acc[8][6];
    #pragma unroll
    for (int r = 0; r < 8; ++r)
        #pragma unroll
        for (int p = 0; p < 6; ++p) acc[r][p] = 0ull;

    #pragma unroll 1
    for (int kc = 0; kc < 8; ++kc) {
        float4 wr[6];
        if (kc < 7) {
            #pragma unroll
            for (int i = 0; i < 6; ++i)
                wr[i] = *(const float4*)(wsrc[i] + (kc + 1) * 32 * H);
        }
        const float* Wb = Wbuf + (kc & 1) * (32 * N3);
        const float* Xk = Xs + kc * 32;
        #pragma unroll 4
        for (int kk = 0; kk < 32; ++kk) {
            unsigned long long w2[6];
            const unsigned long long* wp = (const unsigned long long*)(Wb + kk * N3);
            #pragma unroll
            for (int p = 0; p < 6; ++p) w2[p] = wp[tx + 16 * p];
            unsigned long long a2[8];
            #pragma unroll
            for (int r = 0; r < 8; ++r) {
                float a = Xk[(ty + 16 * r) * E + kk];
                PACK2(a2[r], a);
            }
            #pragma unroll
            for (int r = 0; r < 8; ++r)
                #pragma unroll
                for (int p = 0; p < 6; ++p)
                    FMA2(acc[r][p], a2[r], w2[p]);
        }
        if (kc < 7) {
            float4* wd = (float4*)(Wbuf + ((kc + 1) & 1) * (32 * N3));
            #pragma unroll
            for (int i = 0; i < 6; ++i)
                wd[i * 256 + tid] = wr[i];
        }
        __syncthreads();
    }

    // Store QKV to smem (overwrites dead Xs region; stride 196)
    float* QKV = sm;
    #pragma unroll
    for (int r = 0; r < 8; ++r) {
        int row = ty + 16 * r;
        unsigned long long* qd = (unsigned long long*)(QKV + row * QKV_STRIDE);
        #pragma unroll
        for (int p = 0; p < 6; ++p)
            qd[tx + 16 * p] = acc[r][p];
    }
    __syncthreads();

    // ---------------- Phase 2: causal attention ----------------
    // 2 threads per query row: thread (row, half). half splits j by parity for
    // scores/softmax, and splits the 64 output dims (32 each) for PV.
    float* S   = sm + S_OFF;
    float* red = sm + RED_OFF;   // [0..255] row max, [256..511] row sum
    const int row  = tid & 127;
    const int half = tid >> 7;

    unsigned long long q2[32];
    {
        const unsigned long long* qp = (const unsigned long long*)(QKV + row * QKV_STRIDE);
        #pragma unroll
        for (int d = 0; d < 32; ++d) q2[d] = qp[d];
    }

    // scores for j ≡ half (mod 2), j <= row
    float mloc = __int_as_float(0xff800000);  // -inf
    for (int j = half; j <= row; j += 2) {
        const unsigned long long* kp = (const unsigned long long*)(QKV + j * QKV_STRIDE + H);
        unsigned long long sa[4];
        sa[0] = sa[1] = sa[2] = sa[3] = 0ull;
        #pragma unroll
        for (int d = 0; d < 32; ++d)
            FMA2(sa[d & 3], q2[d], kp[d]);
        float s = 0.f;
        #pragma unroll
        for (int t = 0; t < 4; ++t) {
            float lo, hi; UNPK2(lo, hi, sa[t]);
            s += lo + hi;
        }
        s *= 0.125f;                       // 1/sqrt(64)
        mloc = fmaxf(mloc, s);
        S[row * S_STRIDE + j] = s;
    }
    red[half * 128 + row] = mloc;
    __syncthreads();

    const float m = fmaxf(red[row], red[128 + row]);
    float sloc = 0.f;
    for (int j = half; j <= row; j += 2) {
        float p = __expf(S[row * S_STRIDE + j] - m);
        S[row * S_STRIDE + j] = p;
        sloc += p;
    }
    red[256 + half * 128 + row] = sloc;
    __syncthreads();
    const float inv = 1.f / (red[256 + row] + red[256 + 128 + row]);

    // out[row][32*half : 32*half+32] = sum_j p_j * V_j
    unsigned long long o2[16];
    #pragma unroll
    for (int d = 0; d < 16; ++d) o2[d] = 0ull;
    for (int j = 0; j <= row; ++j) {
        float p = S[row * S_STRIDE + j];
        unsigned long long p2; PACK2(p2, p);
        const unsigned long long* vp =
            (const unsigned long long*)(QKV + j * QKV_STRIDE + 2 * H + 32 * half);
        #pragma unroll
        for (int d = 0; d < 16; ++d)
            FMA2(o2[d], p2, vp[d]);
    }

    float* op = out + ((size_t)b * T + row) * H + 32 * half;
    #pragma unroll
    for (int d = 0; d < 16; ++d) {
        float lo, hi; UNPK2(lo, hi, o2[d]);
        float2 v; v.x = lo * inv; v.y = hi * inv;
        *(float2*)(op + 2 * d) = v;
    }
}

extern "C" void kernel_launch(void* const* d_in, const int* in_sizes, int n_in,
                              void* d_out, int out_size)
{
    using namespace cfg;
    const float* x  = (const float*)d_in[0];
    const float* Wq = (const float*)d_in[1];
    const float* Wk = (const float*)d_in[2];
    const float* Wv = (const float*)d_in[3];
    float* out = (float*)d_out;

    const int B = in_sizes[0] / (T * E);   // 4096

    cudaFuncSetAttribute(attn_head_kernel,
                         cudaFuncAttributeMaxDynamicSharedMemorySize, SMEM_BYTES);
    attn_head_kernel<<<B, 256, SMEM_BYTES>>>(x, Wq, Wk, Wv, out);
}

// round 6
// speedup vs baseline: 1.5324x; 1.5324x over previous
#include <cuda_runtime.h>
#include <cstdint>
#include <cstddef>

// ---------------------------------------------------------------------------
// Packed fp32x2 helpers (phase-2 attention)
// ---------------------------------------------------------------------------
#define FMA2(d, a, b) asm("fma.rn.f32x2 %0, %1, %2, %0;" : "+l"(d) : "l"(a), "l"(b))
#define PACK2(d, f)   asm("mov.b64 %0, {%1, %1};" : "=l"(d) : "f"(f))
#define UNPK2(lo, hi, v) asm("mov.b64 {%0, %1}, %2;" : "=f"(lo), "=f"(hi) : "l"(v))

namespace cfg {
constexpr int T  = 128;
constexpr int E  = 256;
constexpr int H  = 64;
constexpr int N3 = 192;               // Q|K|V
constexpr int QKV_STRIDE = 196;       // floats, padded
constexpr int S_STRIDE   = 129;

// GEMM smem images (bytes). Rows are 256B (128 bf16 = one K-chunk),
// 16B units xor-swizzled: unit j stored at (j ^ (row&7)).
constexpr int AHI_B = 0;              // x_hi   [128][256B] = 32768
constexpr int ALO_B = 32768;          // x_lo   [128][256B] = 32768
constexpr int BHI_B = 65536;          // W^T_hi [192][256B] = 49152
constexpr int BLO_B = 114688;         // W^T_lo [192][256B] = 49152 -> 163840

// Phase-2 float offsets (overlap GEMM bufs; used only after GEMM done)
constexpr int S_OFF_F   = T * QKV_STRIDE;            // 25088
constexpr int RED_OFF_F = S_OFF_F + T * S_STRIDE;    // 41600
constexpr int SMEM_BYTES = (RED_OFF_F + 512) * 4;    // 168448
}

// W^T bf16 hi/lo swizzled images: [chunk(2)][row n(192)][256B]
__device__ __align__(16) unsigned char g_Bhi[2 * 49152];
__device__ __align__(16) unsigned char g_Blo[2 * 49152];

// ---------------------------------------------------------------------------
static __device__ __forceinline__ uint32_t smem_u32(const void* p) {
    uint32_t a;
    asm("{ .reg .u64 t; cvta.to.shared.u64 t, %1; cvt.u32.u64 %0, t; }" : "=r"(a) : "l"(p));
    return a;
}
static __device__ __forceinline__ uint32_t pkbf(float lo, float hi) {
    uint32_t r;  // upper = bf16(hi), lower = bf16(lo): memory order lo first
    asm("cvt.rn.bf16x2.f32 %0, %1, %2;" : "=r"(r) : "f"(hi), "f"(lo));
    return r;
}
static __device__ __forceinline__ void split2(float f0, float f1, uint32_t& h, uint32_t& l) {
    h = pkbf(f0, f1);
    float r0 = f0 - __uint_as_float(h << 16);
    float r1 = f1 - __uint_as_float(h & 0xffff0000u);
    l = pkbf(r0, r1);
}
static __device__ __forceinline__ void ldsm4(uint32_t r[4], uint32_t addr) {
    asm volatile("ldmatrix.sync.aligned.m8n8.x4.shared.b16 {%0,%1,%2,%3}, [%4];"
                 : "=r"(r[0]), "=r"(r[1]), "=r"(r[2]), "=r"(r[3]) : "r"(addr));
}
static __device__ __forceinline__ void mma16816(float d[4],
                                                const uint32_t a[4],
                                                uint32_t b0, uint32_t b1) {
    asm volatile(
        "mma.sync.aligned.m16n8k16.row.col.f32.bf16.bf16.f32 "
        "{%0,%1,%2,%3}, {%4,%5,%6,%7}, {%8,%9}, {%0,%1,%2,%3};"
        : "+f"(d[0]), "+f"(d[1]), "+f"(d[2]), "+f"(d[3])
        : "r"(a[0]), "r"(a[1]), "r"(a[2]), "r"(a[3]), "r"(b0), "r"(b1));
}

// ---------------------------------------------------------------------------
// Pre-kernel: build swizzled bf16 hi/lo images of W^T ([n][k], k contiguous).
// One 16B unit = 8 consecutive k for one row n. 6144 units total.
// ---------------------------------------------------------------------------
__global__ void build_w_images(const float* __restrict__ Wq,
                               const float* __restrict__ Wk,
                               const float* __restrict__ Wv)
{
    int gid = blockIdx.x * blockDim.x + threadIdx.x;   // 0..6143
    int c   = gid / 3072;                              // k-chunk of 128
    int u   = gid % 3072;
    int n   = u >> 4;                                  // 0..191
    int j   = u & 15;                                  // 16B unit within row
    int k0  = c * 128 + j * 8;

    const float* Wsrc = (n < 64) ? (Wq + n) : (n < 128) ? (Wk + n - 64) : (Wv + n - 128);
    float f[8];
    #pragma unroll
    for (int e = 0; e < 8; ++e) f[e] = Wsrc[(size_t)(k0 + e) * cfg::H];

    uint32_t h[4], l[4];
    #pragma unroll
    for (int p = 0; p < 4; ++p) split2(f[2 * p], f[2 * p + 1], h[p], l[p]);

    size_t off = (size_t)c * 49152 + (size_t)n * 256 + (size_t)((j ^ (n & 7)) << 4);
    *(uint4*)(g_Bhi + off) = make_uint4(h[0], h[1], h[2], h[3]);
    *(uint4*)(g_Blo + off) = make_uint4(l[0], l[1], l[2], l[3]);
}

// ---------------------------------------------------------------------------
// Main kernel: one CTA per batch. mma.sync bf16-split QKV + fp32 attention.
// ---------------------------------------------------------------------------
__global__ __launch_bounds__(256, 1)
void attn_head_kernel(const float* __restrict__ x,
                      float* __restrict__ out)
{
    using namespace cfg;
    extern __shared__ __align__(1024) unsigned char smraw[];
    unsigned char* smc = smraw;
    float*         smp = (float*)smraw;

    const int tid = threadIdx.x;
    const int wid = tid >> 5;
    const int lid = tid & 31;
    const int b   = blockIdx.x;

    const uint32_t sb = smem_u32(smraw);

    // Warp tile: rows mbase..mbase+31, cols nbase..nbase+95
    const int mbase = (wid >> 1) * 32;
    const int nbase = (wid & 1) * 96;

    // ldmatrix per-thread invariant address pieces
    const int arow  = mbase + (lid & 7) + ((lid >> 3) & 1) * 8;   // A matrices 0/1 rows
    const int axor  = arow & 7;
    const int ajsel = (lid >> 4) & 1;                             // A matrices 2/3 = k-hi
    const uint32_t aHiRow = sb + AHI_B + arow * 256;
    const uint32_t aLoRow = sb + ALO_B + arow * 256;

    const int brow  = nbase + (lid & 7) + ((lid >> 4) & 1) * 8;   // B matrices 0,1 / 2,3 rows
    const int bxor  = brow & 7;
    const int bjsel = (lid >> 3) & 1;                             // within-pair: k-lo/k-hi
    const uint32_t bHiRow = sb + BHI_B + brow * 256;
    const uint32_t bLoRow = sb + BLO_B + brow * 256;

    float acc[2][12][4];
    #pragma unroll
    for (int mt = 0; mt < 2; ++mt)
        #pragma unroll
        for (int nt = 0; nt < 12; ++nt)
            #pragma unroll
            for (int r = 0; r < 4; ++r) acc[mt][nt][r] = 0.f;

    #pragma unroll 1
    for (int chunk = 0; chunk < 2; ++chunk) {
        // ---- Stage A: convert x chunk -> swizzled bf16 hi/lo ----
        #pragma unroll
        for (int i = 0; i < 8; ++i) {
            int u   = i * 256 + tid;          // 0..2047
            int row = u >> 4;
            int j   = u & 15;
            const float4* src =
                (const float4*)(x + (size_t)b * (T * E) + (size_t)row * E + chunk * 128 + j * 8);
            float4 fa = src[0], fb = src[1];
            uint32_t h0, h1, h2, h3, l0, l1, l2, l3;
            split2(fa.x, fa.y, h0, l0);
            split2(fa.z, fa.w, h1, l1);
            split2(fb.x, fb.y, h2, l2);
            split2(fb.z, fb.w, h3, l3);
            int off = row * 256 + ((j ^ (row & 7)) << 4);
            *(uint4*)(smc + AHI_B + off) = make_uint4(h0, h1, h2, h3);
            *(uint4*)(smc + ALO_B + off) = make_uint4(l0, l1, l2, l3);
        }
        // ---- Stage B: copy prebuilt W images (coalesced, L2-hot) ----
        #pragma unroll
        for (int i = 0; i < 12; ++i) {
            int u = i * 256 + tid;            // 0..3071
            *(uint4*)(smc + BHI_B + u * 16) = *(const uint4*)(g_Bhi + (size_t)chunk * 49152 + u * 16);
            *(uint4*)(smc + BLO_B + u * 16) = *(const uint4*)(g_Blo + (size_t)chunk * 49152 + u * 16);
        }
        __syncthreads();

        // ---- 8 k16-steps of split-bf16 mma ----
        #pragma unroll 1
        for (int s = 0; s < 8; ++s) {
            const int ja = 2 * s + ajsel;
            const int jb = 2 * s + bjsel;
            const uint32_t aoff = (uint32_t)((ja ^ axor) << 4);
            const uint32_t boff = (uint32_t)((jb ^ bxor) << 4);

            uint32_t ah[2][4], al[2][4];
            ldsm4(ah[0], aHiRow + aoff);
            ldsm4(al[0], aLoRow + aoff);
            ldsm4(ah[1], aHiRow + 16 * 256 + aoff);
            ldsm4(al[1], aLoRow + 16 * 256 + aoff);

            #pragma unroll
            for (int g = 0; g < 6; ++g) {
                uint32_t bh[4], bl[4];
                ldsm4(bh, bHiRow + g * 16 * 256 + boff);
                ldsm4(bl, bLoRow + g * 16 * 256 + boff);
                #pragma unroll
                for (int mt = 0; mt < 2; ++mt) {
                    #pragma unroll
                    for (int nn = 0; nn < 2; ++nn) {
                        float* d = acc[mt][g * 2 + nn];
                        mma16816(d, ah[mt], bh[2 * nn], bh[2 * nn + 1]);
                        mma16816(d, ah[mt], bl[2 * nn], bl[2 * nn + 1]);
                        mma16816(d, al[mt], bh[2 * nn], bh[2 * nn + 1]);
                    }
                }
            }
        }
        __syncthreads();   // smem dead before next chunk overwrites
    }

    // ---- Epilogue: fragments -> QKV smem (stride 196, fp32) ----
    {
        float* QKV = smp;
        const int r0 = (lid >> 2);
        const int c0 = (lid & 3) * 2;
        #pragma unroll
        for (int mt = 0; mt < 2; ++mt) {
            #pragma unroll
            for (int nt = 0; nt < 12; ++nt) {
                int row = mbase + mt * 16 + r0;
                int col = nbase + nt * 8 + c0;
                float2 v0; v0.x = acc[mt][nt][0]; v0.y = acc[mt][nt][1];
                float2 v1; v1.x = acc[mt][nt][2]; v1.y = acc[mt][nt][3];
                *(float2*)(QKV + row * QKV_STRIDE + col)       = v0;
                *(float2*)(QKV + (row + 8) * QKV_STRIDE + col) = v1;
            }
        }
    }
    __syncthreads();

    // ---- Phase 2: causal attention (fp32 / FMA2), unchanged from R4 ----
    float* QKV = smp;
    float* S   = smp + S_OFF_F;
    float* red = smp + RED_OFF_F;
    const int row  = tid & 127;
    const int half = tid >> 7;

    unsigned long long q2[32];
    {
        const unsigned long long* qp = (const unsigned long long*)(QKV + row * QKV_STRIDE);
        #pragma unroll
        for (int d = 0; d < 32; ++d) q2[d] = qp[d];
    }

    float mloc = __int_as_float(0xff800000);
    for (int j = half; j <= row; j += 2) {
        const unsigned long long* kp = (const unsigned long long*)(QKV + j * QKV_STRIDE + H);
        unsigned long long sa[4];
        sa[0] = sa[1] = sa[2] = sa[3] = 0ull;
        #pragma unroll
        for (int d = 0; d < 32; ++d)
            FMA2(sa[d & 3], q2[d], kp[d]);
        float s = 0.f;
        #pragma unroll
        for (int t = 0; t < 4; ++t) {
            float lo, hi; UNPK2(lo, hi, sa[t]);
            s += lo + hi;
        }
        s *= 0.125f;
        mloc = fmaxf(mloc, s);
        S[row * S_STRIDE + j] = s;
    }
    red[half * 128 + row] = mloc;
    __syncthreads();

    const float m = fmaxf(red[row], red[128 + row]);
    float sloc = 0.f;
    for (int j = half; j <= row; j += 2) {
        float p = __expf(S[row * S_STRIDE + j] - m);
        S[row * S_STRIDE + j] = p;
        sloc += p;
    }
    red[256 + half * 128 + row] = sloc;
    __syncthreads();
    const float inv = 1.f / (red[256 + row] + red[256 + 128 + row]);

    unsigned long long o2[16];
    #pragma unroll
    for (int d = 0; d < 16; ++d) o2[d] = 0ull;
    for (int j = 0; j <= row; ++j) {
        float p = S[row * S_STRIDE + j];
        unsigned long long p2; PACK2(p2, p);
        const unsigned long long* vp =
            (const unsigned long long*)(QKV + j * QKV_STRIDE + 2 * H + 32 * half);
        #pragma unroll
        for (int d = 0; d < 16; ++d)
            FMA2(o2[d], p2, vp[d]);
    }

    float* op = out + ((size_t)b * T + row) * H + 32 * half;
    #pragma unroll
    for (int d = 0; d < 16; ++d) {
        float lo, hi; UNPK2(lo, hi, o2[d]);
        float2 v; v.x = lo * inv; v.y = hi * inv;
        *(float2*)(op + 2 * d) = v;
    }
}

// ---------------------------------------------------------------------------
extern "C" void kernel_launch(void* const* d_in, const int* in_sizes, int n_in,
                              void* d_out, int out_size)
{
    using namespace cfg;
    const float* x  = (const float*)d_in[0];
    const float* Wq = (const float*)d_in[1];
    const float* Wk = (const float*)d_in[2];
    const float* Wv = (const float*)d_in[3];
    float* out = (float*)d_out;

    const int B = in_sizes[0] / (T * E);

    build_w_images<<<24, 256>>>(Wq, Wk, Wv);

    cudaFuncSetAttribute(attn_head_kernel,
                         cudaFuncAttributeMaxDynamicSharedMemorySize, SMEM_BYTES);
    attn_head_kernel<<<B, 256, SMEM_BYTES>>>(x, out);
}

// round 8
// speedup vs baseline: 2.6622x; 1.7373x over previous
#include <cuda_runtime.h>
#include <cstdint>
#include <cstddef>

namespace cfg {
constexpr int T  = 128;
constexpr int E  = 256;
constexpr int H  = 64;

// GEMM smem images (bytes). Rows are 256B (128 bf16 = one K-chunk),
// 16B units xor-swizzled: unit j stored at (j ^ (row&7)).
constexpr int AHI_B = 0;              // x_hi   [128][256B] = 32768
constexpr int ALO_B = 32768;          // x_lo   [128][256B] = 32768
constexpr int BHI_B = 65536;          // W^T_hi [192][256B] = 49152
constexpr int BLO_B = 114688;         // W^T_lo [192][256B] = 49152 -> 163840

// Attention images (overlay GEMM A region + start of BHI; used post-GEMM).
// [128 rows][64 bf16 = 128B], 16B units xor-swizzled by (row&7).
constexpr int QHI_B = 0;
constexpr int QLO_B = 16384;
constexpr int KHI_B = 32768;
constexpr int KLO_B = 49152;
constexpr int VHI_B = 65536;
constexpr int VLO_B = 81920;          // ends 98304

constexpr int SMEM_BYTES = 163840;
}

// W^T bf16 hi/lo swizzled images: [chunk(2)][row n(192)][256B]
__device__ __align__(16) unsigned char g_Bhi[2 * 49152];
__device__ __align__(16) unsigned char g_Blo[2 * 49152];

// ---------------------------------------------------------------------------
static __device__ __forceinline__ uint32_t smem_u32(const void* p) {
    uint32_t a;
    asm("{ .reg .u64 t; cvta.to.shared.u64 t, %1; cvt.u32.u64 %0, t; }" : "=r"(a) : "l"(p));
    return a;
}
static __device__ __forceinline__ uint32_t pkbf(float lo, float hi) {
    uint32_t r;  // upper = bf16(hi), lower = bf16(lo)
    asm("cvt.rn.bf16x2.f32 %0, %1, %2;" : "=r"(r) : "f"(hi), "f"(lo));
    return r;
}
static __device__ __forceinline__ void split2(float f0, float f1, uint32_t& h, uint32_t& l) {
    h = pkbf(f0, f1);
    float r0 = f0 - __uint_as_float(h << 16);
    float r1 = f1 - __uint_as_float(h & 0xffff0000u);
    l = pkbf(r0, r1);
}
static __device__ __forceinline__ void ldsm4(uint32_t r[4], uint32_t addr) {
    asm volatile("ldmatrix.sync.aligned.m8n8.x4.shared.b16 {%0,%1,%2,%3}, [%4];"
                 : "=r"(r[0]), "=r"(r[1]), "=r"(r[2]), "=r"(r[3]) : "r"(addr));
}
static __device__ __forceinline__ void ldsm4t(uint32_t r[4], uint32_t addr) {
    asm volatile("ldmatrix.sync.aligned.m8n8.x4.trans.shared.b16 {%0,%1,%2,%3}, [%4];"
                 : "=r"(r[0]), "=r"(r[1]), "=r"(r[2]), "=r"(r[3]) : "r"(addr));
}
static __device__ __forceinline__ void mma16816(float d[4],
                                                const uint32_t a[4],
                                                uint32_t b0, uint32_t b1) {
    asm volatile(
        "mma.sync.aligned.m16n8k16.row.col.f32.bf16.bf16.f32 "
        "{%0,%1,%2,%3}, {%4,%5,%6,%7}, {%8,%9}, {%0,%1,%2,%3};"
        : "+f"(d[0]), "+f"(d[1]), "+f"(d[2]), "+f"(d[3])
        : "r"(a[0]), "r"(a[1]), "r"(a[2]), "r"(a[3]), "r"(b0), "r"(b1));
}

// ---------------------------------------------------------------------------
// Pre-kernel: build swizzled bf16 hi/lo images of W^T ([n][k], k contiguous).
// ---------------------------------------------------------------------------
__global__ void build_w_images(const float* __restrict__ Wq,
                               const float* __restrict__ Wk,
                               const float* __restrict__ Wv)
{
    int gid = blockIdx.x * blockDim.x + threadIdx.x;   // 0..6143
    int c   = gid / 3072;                              // k-chunk of 128
    int u   = gid % 3072;
    int n   = u >> 4;                                  // 0..191
    int j   = u & 15;                                  // 16B unit within row
    int k0  = c * 128 + j * 8;

    const float* Wsrc = (n < 64) ? (Wq + n) : (n < 128) ? (Wk + n - 64) : (Wv + n - 128);
    float f[8];
    #pragma unroll
    for (int e = 0; e < 8; ++e) f[e] = Wsrc[(size_t)(k0 + e) * cfg::H];

    uint32_t h[4], l[4];
    #pragma unroll
    for (int p = 0; p < 4; ++p) split2(f[2 * p], f[2 * p + 1], h[p], l[p]);

    size_t off = (size_t)c * 49152 + (size_t)n * 256 + (size_t)((j ^ (n & 7)) << 4);
    *(uint4*)(g_Bhi + off) = make_uint4(h[0], h[1], h[2], h[3]);
    *(uint4*)(g_Blo + off) = make_uint4(l[0], l[1], l[2], l[3]);
}

// ---------------------------------------------------------------------------
// Main kernel: one CTA per batch. Fully tensor-core (split-bf16) pipeline.
// ---------------------------------------------------------------------------
__global__ __launch_bounds__(256, 1)
void attn_head_kernel(const float* __restrict__ x,
                      float* __restrict__ out)
{
    using namespace cfg;
    extern __shared__ __align__(1024) unsigned char smraw[];
    unsigned char* smc = smraw;

    const int tid = threadIdx.x;
    const int wid = tid >> 5;
    const int lid = tid & 31;
    const int b   = blockIdx.x;

    const uint32_t sb = smem_u32(smraw);

    // ===================== Phase 1: QKV GEMM (as R6) =====================
    const int mbase = (wid >> 1) * 32;
    const int nbase = (wid & 1) * 96;

    const int arow  = mbase + (lid & 7) + ((lid >> 3) & 1) * 8;
    const int axor  = arow & 7;
    const int ajsel = (lid >> 4) & 1;
    const uint32_t aHiRow = sb + AHI_B + arow * 256;
    const uint32_t aLoRow = sb + ALO_B + arow * 256;

    const int brow  = nbase + (lid & 7) + ((lid >> 4) & 1) * 8;
    const int bxor  = brow & 7;
    const int bjsel = (lid >> 3) & 1;
    const uint32_t bHiRow = sb + BHI_B + brow * 256;
    const uint32_t bLoRow = sb + BLO_B + brow * 256;

    float acc[2][12][4];
    #pragma unroll
    for (int mt = 0; mt < 2; ++mt)
        #pragma unroll
        for (int nt = 0; nt < 12; ++nt)
            #pragma unroll
            for (int r = 0; r < 4; ++r) acc[mt][nt][r] = 0.f;

    #pragma unroll 1
    for (int chunk = 0; chunk < 2; ++chunk) {
        #pragma unroll
        for (int i = 0; i < 8; ++i) {
            int u   = i * 256 + tid;
            int row = u >> 4;
            int j   = u & 15;
            const float4* src =
                (const float4*)(x + (size_t)b * (T * E) + (size_t)row * E + chunk * 128 + j * 8);
            float4 fa = src[0], fb = src[1];
            uint32_t h0, h1, h2, h3, l0, l1, l2, l3;
            split2(fa.x, fa.y, h0, l0);
            split2(fa.z, fa.w, h1, l1);
            split2(fb.x, fb.y, h2, l2);
            split2(fb.z, fb.w, h3, l3);
            int off = row * 256 + ((j ^ (row & 7)) << 4);
            *(uint4*)(smc + AHI_B + off) = make_uint4(h0, h1, h2, h3);
            *(uint4*)(smc + ALO_B + off) = make_uint4(l0, l1, l2, l3);
        }
        #pragma unroll
        for (int i = 0; i < 12; ++i) {
            int u = i * 256 + tid;
            *(uint4*)(smc + BHI_B + u * 16) = *(const uint4*)(g_Bhi + (size_t)chunk * 49152 + u * 16);
            *(uint4*)(smc + BLO_B + u * 16) = *(const uint4*)(g_Blo + (size_t)chunk * 49152 + u * 16);
        }
        __syncthreads();

        #pragma unroll 1
        for (int s = 0; s < 8; ++s) {
            const int ja = 2 * s + ajsel;
            const int jb = 2 * s + bjsel;
            const uint32_t aoff = (uint32_t)((ja ^ axor) << 4);
            const uint32_t boff = (uint32_t)((jb ^ bxor) << 4);

            uint32_t ah[2][4], al[2][4];
            ldsm4(ah[0], aHiRow + aoff);
            ldsm4(al[0], aLoRow + aoff);
            ldsm4(ah[1], aHiRow + 16 * 256 + aoff);
            ldsm4(al[1], aLoRow + 16 * 256 + aoff);

            #pragma unroll
            for (int g = 0; g < 6; ++g) {
                uint32_t bh[4], bl[4];
                ldsm4(bh, bHiRow + g * 16 * 256 + boff);
                ldsm4(bl, bLoRow + g * 16 * 256 + boff);
                #pragma unroll
                for (int mt = 0; mt < 2; ++mt) {
                    #pragma unroll
                    for (int nn = 0; nn < 2; ++nn) {
                        float* d = acc[mt][g * 2 + nn];
                        mma16816(d, ah[mt], bh[2 * nn], bh[2 * nn + 1]);
                        mma16816(d, ah[mt], bl[2 * nn], bl[2 * nn + 1]);
                        mma16816(d, al[mt], bh[2 * nn], bh[2 * nn + 1]);
                    }
                }
            }
        }
        __syncthreads();
    }

    // ===== Epilogue: fragments -> split-bf16 Q(K,V) images (Q pre-scaled 1/8) =====
    {
        const int r0 = lid >> 2;
        const int c4 = lid & 3;
        #pragma unroll
        for (int mt = 0; mt < 2; ++mt) {
            #pragma unroll
            for (int nt = 0; nt < 12; ++nt) {
                int n = nbase + 8 * nt;
                int hiB, loB, m;
                float sc;
                if (n < 64)       { hiB = QHI_B; loB = QLO_B; m = n;       sc = 0.125f; }
                else if (n < 128) { hiB = KHI_B; loB = KLO_B; m = n - 64;  sc = 1.f; }
                else              { hiB = VHI_B; loB = VLO_B; m = n - 128; sc = 1.f; }
                int u   = m >> 3;
                int row = mbase + mt * 16 + r0;
                uint32_t h0, l0, h1, l1;
                split2(sc * acc[mt][nt][0], sc * acc[mt][nt][1], h0, l0);
                split2(sc * acc[mt][nt][2], sc * acc[mt][nt][3], h1, l1);
                int byt0 = row * 128 + ((u ^ (row & 7)) << 4) + c4 * 4;
                int rw8  = row + 8;
                int byt1 = rw8 * 128 + ((u ^ (rw8 & 7)) << 4) + c4 * 4;
                *(uint32_t*)(smc + hiB + byt0) = h0;
                *(uint32_t*)(smc + loB + byt0) = l0;
                *(uint32_t*)(smc + hiB + byt1) = h1;
                *(uint32_t*)(smc + loB + byt1) = l1;
            }
        }
    }
    __syncthreads();

    // ===================== Phase 2: tensor-core attention =====================
    // Warp wid owns query rows [16*wid, 16*wid+16).
    const int rw    = wid * 16;
    const int rofsA = (lid & 7) + ((lid >> 3) & 1) * 8;   // A-frag rows / V k-rows
    const int jselA = (lid >> 4) & 1;
    const int rofsK = (lid & 7) + ((lid >> 4) & 1) * 8;   // B-frag n-rows
    const int jselK = (lid >> 3) & 1;
    const int xorr  = lid & 7;
    const int vub   = (lid >> 4) & 1;                     // V n-unit bit

    // Q A-fragments (4 k16 steps over H=64)
    uint32_t qh[4][4], ql[4][4];
    #pragma unroll
    for (int s = 0; s < 4; ++s) {
        uint32_t off = (uint32_t)((rw + rofsA) * 128 + (((2 * s + jselA) ^ xorr) << 4));
        ldsm4(qh[s], sb + QHI_B + off);
        ldsm4(ql[s], sb + QLO_B + off);
    }

    // S = (Q/8)·K^T, causal blocks only
    float sacc[16][4];
    #pragma unroll
    for (int nb = 0; nb < 16; ++nb)
        #pragma unroll
        for (int i = 0; i < 4; ++i) sacc[nb][i] = 0.f;

    #pragma unroll
    for (int pb = 0; pb < 8; ++pb) {
        if (pb <= wid) {
            #pragma unroll
            for (int s = 0; s < 4; ++s) {
                uint32_t off = (uint32_t)((16 * pb + rofsK) * 128 +
                                          (((2 * s + jselK) ^ xorr) << 4));
                uint32_t kh[4], kl[4];
                ldsm4(kh, sb + KHI_B + off);
                ldsm4(kl, sb + KLO_B + off);
                #pragma unroll
                for (int nn = 0; nn < 2; ++nn) {
                    float* d = sacc[2 * pb + nn];
                    mma16816(d, qh[s], kh[2 * nn], kh[2 * nn + 1]);
                    mma16816(d, qh[s], kl[2 * nn], kl[2 * nn + 1]);
                    mma16816(d, ql[s], kh[2 * nn], kh[2 * nn + 1]);
                }
            }
        }
    }

    // Mask + register softmax (quad shuffles; rows r0 and r0+8)
    const int r0 = lid >> 2;
    const int cq = (lid & 3) * 2;
    const int rowh = rw + r0;
    const int rowl = rowh + 8;

    float m0 = -1e30f, m1 = -1e30f;
    #pragma unroll
    for (int nb = 0; nb < 16; ++nb) {
        if (nb <= 2 * wid + 1) {
            if (nb >= 2 * wid) {
                int colb = 8 * nb + cq;
                if (colb     > rowh) sacc[nb][0] = -1e30f;
                if (colb + 1 > rowh) sacc[nb][1] = -1e30f;
                if (colb     > rowl) sacc[nb][2] = -1e30f;
                if (colb + 1 > rowl) sacc[nb][3] = -1e30f;
            }
            m0 = fmaxf(m0, fmaxf(sacc[nb][0], sacc[nb][1]));
            m1 = fmaxf(m1, fmaxf(sacc[nb][2], sacc[nb][3]));
        }
    }
    m0 = fmaxf(m0, __shfl_xor_sync(0xffffffffu, m0, 1));
    m0 = fmaxf(m0, __shfl_xor_sync(0xffffffffu, m0, 2));
    m1 = fmaxf(m1, __shfl_xor_sync(0xffffffffu, m1, 1));
    m1 = fmaxf(m1, __shfl_xor_sync(0xffffffffu, m1, 2));

    float s0 = 0.f, s1 = 0.f;
    #pragma unroll
    for (int nb = 0; nb < 16; ++nb) {
        if (nb <= 2 * wid + 1) {
            sacc[nb][0] = __expf(sacc[nb][0] - m0);
            sacc[nb][1] = __expf(sacc[nb][1] - m0);
            sacc[nb][2] = __expf(sacc[nb][2] - m1);
            sacc[nb][3] = __expf(sacc[nb][3] - m1);
            s0 += sacc[nb][0] + sacc[nb][1];
            s1 += sacc[nb][2] + sacc[nb][3];
        }
    }
    s0 += __shfl_xor_sync(0xffffffffu, s0, 1);
    s0 += __shfl_xor_sync(0xffffffffu, s0, 2);
    s1 += __shfl_xor_sync(0xffffffffu, s1, 1);
    s1 += __shfl_xor_sync(0xffffffffu, s1, 2);
    const float inv0 = 1.f / s0;
    const float inv1 = 1.f / s1;

    // P fragments (split bf16) straight from S accumulators
    uint32_t ph[8][4], pl[8][4];
    #pragma unroll
    for (int t = 0; t < 8; ++t) {
        if (t <= wid) {
            split2(sacc[2 * t][0],     sacc[2 * t][1],     ph[t][0], pl[t][0]);
            split2(sacc[2 * t][2],     sacc[2 * t][3],     ph[t][1], pl[t][1]);
            split2(sacc[2 * t + 1][0], sacc[2 * t + 1][1], ph[t][2], pl[t][2]);
            split2(sacc[2 * t + 1][2], sacc[2 * t + 1][3], ph[t][3], pl[t][3]);
        }
    }

    // O = P·V  (V B-fragments via ldmatrix.trans on [j][h] image)
    float oacc[8][4];
    #pragma unroll
    for (int nb = 0; nb < 8; ++nb)
        #pragma unroll
        for (int i = 0; i < 4; ++i) oacc[nb][i] = 0.f;

    #pragma unroll
    for (int t = 0; t < 8; ++t) {
        if (t <= wid) {
            #pragma unroll
            for (int pb = 0; pb < 4; ++pb) {
                uint32_t off = (uint32_t)((16 * t + rofsA) * 128 +
                                          (((2 * pb + vub) ^ xorr) << 4));
                uint32_t vh[4], vl[4];
                ldsm4t(vh, sb + VHI_B + off);
                ldsm4t(vl, sb + VLO_B + off);
                #pragma unroll
                for (int nn = 0; nn < 2; ++nn) {
                    float* d = oacc[2 * pb + nn];
                    mma16816(d, ph[t], vh[2 * nn], vh[2 * nn + 1]);
                    mma16816(d, ph[t], vl[2 * nn], vl[2 * nn + 1]);
                    mma16816(d, pl[t], vh[2 * nn], vh[2 * nn + 1]);
                }
            }
        }
    }

    // Scale by 1/rowsum and write out
    float* ob = out + (size_t)b * T * H;
    #pragma unroll
    for (int nb = 0; nb < 8; ++nb) {
        int col = 8 * nb + cq;
        float2 v0; v0.x = oacc[nb][0] * inv0; v0.y = oacc[nb][1] * inv0;
        float2 v1; v1.x = oacc[nb][2] * inv1; v1.y = oacc[nb][3] * inv1;
        *(float2*)(ob + rowh * H + col) = v0;
        *(float2*)(ob + rowl * H + col) = v1;
    }
}

// ---------------------------------------------------------------------------
extern "C" void kernel_launch(void* const* d_in, const int* in_sizes, int n_in,
                              void* d_out, int out_size)
{
    using namespace cfg;
    const float* x  = (const float*)d_in[0];
    const float* Wq = (const float*)d_in[1];
    const float* Wk = (const float*)d_in[2];
    const float* Wv = (const float*)d_in[3];
    float* out = (float*)d_out;

    const int B = in_sizes[0] / (T * E);

    build_w_images<<<24, 256>>>(Wq, Wk, Wv);

    cudaFuncSetAttribute(attn_head_kernel,
                         cudaFuncAttributeMaxDynamicSharedMemorySize, SMEM_BYTES);
    attn_head_kernel<<<B, 256, SMEM_BYTES>>>(x, out);
}

// round 10
// speedup vs baseline: 3.3063x; 1.2419x over previous
#include <cuda_runtime.h>
#include <cstdint>
#include <cstddef>

namespace cfg {
constexpr int T  = 128;
constexpr int E  = 256;
constexpr int H  = 64;

// GEMM smem (bytes). A rows: 256B = 128 fp16 (one 128-k chunk), 16B units
// xor-swizzled by (row&7). B rows likewise (192 rows, hi only).
constexpr int A0HI_B = 0;        // 32 KB
constexpr int A0LO_B = 32768;    // 32 KB
constexpr int A1HI_B = 65536;    // 32 KB
constexpr int A1LO_B = 98304;    // 32 KB
constexpr int B0HI_B = 131072;   // 48 KB
constexpr int B1HI_B = 180224;   // 48 KB -> 229376
constexpr int SMEM_BYTES = 229376;

// Attention images overlay A region post-GEMM: [128 rows][64 fp16 = 128B],
// 16B units xor-swizzled by (row&7).
constexpr int QHI_B = 0;
constexpr int QLO_B = 16384;
constexpr int KHI_B = 32768;
constexpr int KLO_B = 49152;
constexpr int VHI_B = 65536;
constexpr int VLO_B = 81920;     // ends 98304
}

// W^T fp16 (hi only) swizzled images: [chunk(2)][row n(192)][256B]
__device__ __align__(16) unsigned char g_Wh[2 * 49152];

// ---------------------------------------------------------------------------
static __device__ __forceinline__ uint32_t smem_u32(const void* p) {
    uint32_t a;
    asm("{ .reg .u64 t; cvta.to.shared.u64 t, %1; cvt.u32.u64 %0, t; }" : "=r"(a) : "l"(p));
    return a;
}
static __device__ __forceinline__ uint32_t pkh(float f0, float f1) {
    uint32_t r;  // lower half = f16(f0), upper = f16(f1)
    asm("cvt.rn.f16x2.f32 %0, %1, %2;" : "=r"(r) : "f"(f1), "f"(f0));
    return r;
}
static __device__ __forceinline__ void split2h(float f0, float f1, uint32_t& h, uint32_t& l) {
    h = pkh(f0, f1);
    float g0, g1;
    asm("{.reg .b16 a,b;\n\t mov.b32 {a,b}, %2;\n\t cvt.f32.f16 %0, a;\n\t cvt.f32.f16 %1, b;}"
        : "=f"(g0), "=f"(g1) : "r"(h));
    l = pkh(f0 - g0, f1 - g1);
}
static __device__ __forceinline__ void ldsm4(uint32_t r[4], uint32_t addr) {
    asm volatile("ldmatrix.sync.aligned.m8n8.x4.shared.b16 {%0,%1,%2,%3}, [%4];"
                 : "=r"(r[0]), "=r"(r[1]), "=r"(r[2]), "=r"(r[3]) : "r"(addr));
}
static __device__ __forceinline__ void ldsm4t(uint32_t r[4], uint32_t addr) {
    asm volatile("ldmatrix.sync.aligned.m8n8.x4.trans.shared.b16 {%0,%1,%2,%3}, [%4];"
                 : "=r"(r[0]), "=r"(r[1]), "=r"(r[2]), "=r"(r[3]) : "r"(addr));
}
static __device__ __forceinline__ void mma16816(float d[4],
                                                const uint32_t a[4],
                                                uint32_t b0, uint32_t b1) {
    asm volatile(
        "mma.sync.aligned.m16n8k16.row.col.f32.f16.f16.f32 "
        "{%0,%1,%2,%3}, {%4,%5,%6,%7}, {%8,%9}, {%0,%1,%2,%3};"
        : "+f"(d[0]), "+f"(d[1]), "+f"(d[2]), "+f"(d[3])
        : "r"(a[0]), "r"(a[1]), "r"(a[2]), "r"(a[3]), "r"(b0), "r"(b1));
}
#define CP16(dst, src) \
    asm volatile("cp.async.cg.shared.global [%0], [%1], 16;" :: "r"(dst), "l"(src) : "memory")
#define CPCOMMIT() asm volatile("cp.async.commit_group;" ::: "memory")
#define CPWAIT(n)  asm volatile("cp.async.wait_group %0;" :: "n"(n) : "memory")

// ---------------------------------------------------------------------------
// Pre-kernel: swizzled fp16 image of W^T ([n][k], k contiguous), hi only.
// ---------------------------------------------------------------------------
__global__ void build_w_images(const float* __restrict__ Wq,
                               const float* __restrict__ Wk,
                               const float* __restrict__ Wv)
{
    int gid = blockIdx.x * blockDim.x + threadIdx.x;   // 0..6143
    int c   = gid / 3072;
    int u   = gid % 3072;
    int n   = u >> 4;
    int j   = u & 15;
    int k0  = c * 128 + j * 8;

    const float* Wsrc = (n < 64) ? (Wq + n) : (n < 128) ? (Wk + n - 64) : (Wv + n - 128);
    float f[8];
    #pragma unroll
    for (int e = 0; e < 8; ++e) f[e] = Wsrc[(size_t)(k0 + e) * cfg::H];

    uint32_t h[4];
    #pragma unroll
    for (int p = 0; p < 4; ++p) h[p] = pkh(f[2 * p], f[2 * p + 1]);

    size_t off = (size_t)c * 49152 + (size_t)n * 256 + (size_t)((j ^ (n & 7)) << 4);
    *(uint4*)(g_Wh + off) = make_uint4(h[0], h[1], h[2], h[3]);
}

// ---------------------------------------------------------------------------
// Main kernel: one CTA per batch. fp16 split tensor pipeline, cp.async W.
// ---------------------------------------------------------------------------
__global__ __launch_bounds__(256, 1)
void attn_head_kernel(const float* __restrict__ x,
                      float* __restrict__ out)
{
    using namespace cfg;
    extern __shared__ __align__(1024) unsigned char smraw[];
    unsigned char* smc = smraw;

    const int tid = threadIdx.x;
    const int wid = tid >> 5;
    const int lid = tid & 31;
    const int b   = blockIdx.x;
    const uint32_t sb = smem_u32(smraw);
    const float* xb = x + (size_t)b * (T * E);

    // ===== Kick off W copies for both chunks (hi only), fully async =====
    #pragma unroll
    for (int i = 0; i < 12; ++i) {
        int u = i * 256 + tid;
        CP16(sb + B0HI_B + u * 16, g_Wh + u * 16);
    }
    CPCOMMIT();
    #pragma unroll
    for (int i = 0; i < 12; ++i) {
        int u = i * 256 + tid;
        CP16(sb + B1HI_B + u * 16, g_Wh + 49152 + u * 16);
    }
    CPCOMMIT();

    // ===== x chunk 0 -> A0 hi/lo =====
    #pragma unroll
    for (int i = 0; i < 8; ++i) {
        int u   = i * 256 + tid;
        int row = u >> 4;
        int j   = u & 15;
        const float4* src = (const float4*)(xb + (size_t)row * E + j * 8);
        float4 fa = src[0], fb = src[1];
        uint32_t h0, h1, h2, h3, l0, l1, l2, l3;
        split2h(fa.x, fa.y, h0, l0);
        split2h(fa.z, fa.w, h1, l1);
        split2h(fb.x, fb.y, h2, l2);
        split2h(fb.z, fb.w, h3, l3);
        int off = row * 256 + ((j ^ (row & 7)) << 4);
        *(uint4*)(smc + A0HI_B + off) = make_uint4(h0, h1, h2, h3);
        *(uint4*)(smc + A0LO_B + off) = make_uint4(l0, l1, l2, l3);
    }
    CPWAIT(1);          // B0 resident
    __syncthreads();

    // ===== Warp-tile constants (M 4 x N 2 tiling; tile 32x96) =====
    const int mbase = (wid >> 1) * 32;
    const int nbase = (wid & 1) * 96;
    const int arow  = mbase + (lid & 7) + ((lid >> 3) & 1) * 8;
    const int axor  = arow & 7;
    const int ajsel = (lid >> 4) & 1;
    const int brow  = nbase + (lid & 7) + ((lid >> 4) & 1) * 8;
    const int bxor  = brow & 7;
    const int bjsel = (lid >> 3) & 1;

    float acc[2][12][4];
    #pragma unroll
    for (int mt = 0; mt < 2; ++mt)
        #pragma unroll
        for (int nt = 0; nt < 12; ++nt)
            #pragma unroll
            for (int r = 0; r < 4; ++r) acc[mt][nt][r] = 0.f;

    // One k16-step of the 2-term GEMM (hh + lh)
    auto kstep = [&](uint32_t aHi, uint32_t aLo, uint32_t bB, int s) {
        const uint32_t aoff = (uint32_t)(((2 * s + ajsel) ^ axor) << 4);
        const uint32_t boff = (uint32_t)(((2 * s + bjsel) ^ bxor) << 4);
        uint32_t ah[2][4], al[2][4];
        ldsm4(ah[0], aHi + aoff);
        ldsm4(al[0], aLo + aoff);
        ldsm4(ah[1], aHi + 16 * 256 + aoff);
        ldsm4(al[1], aLo + 16 * 256 + aoff);
        #pragma unroll
        for (int g = 0; g < 6; ++g) {
            uint32_t bh[4];
            ldsm4(bh, bB + g * 16 * 256 + boff);
            #pragma unroll
            for (int mt = 0; mt < 2; ++mt) {
                #pragma unroll
                for (int nn = 0; nn < 2; ++nn) {
                    float* d = acc[mt][g * 2 + nn];
                    mma16816(d, ah[mt], bh[2 * nn], bh[2 * nn + 1]);
                    mma16816(d, al[mt], bh[2 * nn], bh[2 * nn + 1]);
                }
            }
        }
    };

    const uint32_t a0h = sb + A0HI_B + arow * 256;
    const uint32_t a0l = sb + A0LO_B + arow * 256;
    const uint32_t a1h = sb + A1HI_B + arow * 256;
    const uint32_t a1l = sb + A1LO_B + arow * 256;
    const uint32_t b0  = sb + B0HI_B + brow * 256;
    const uint32_t b1  = sb + B1HI_B + brow * 256;

    // ===== MMA chunk 0, with x chunk-1 software-pipelined in =====
    float4 p0, p1;
    {
        int row = tid >> 4, j = tid & 15;
        const float4* src = (const float4*)(xb + (size_t)row * E + 128 + j * 8);
        p0 = src[0]; p1 = src[1];
    }
    #pragma unroll 1
    for (int s = 0; s < 8; ++s) {
        float4 n0, n1;
        if (s < 7) {
            int u = (s + 1) * 256 + tid;
            int row = u >> 4, j = u & 15;
            const float4* src = (const float4*)(xb + (size_t)row * E + 128 + j * 8);
            n0 = src[0]; n1 = src[1];
        }
        kstep(a0h, a0l, b0, s);
        {
            int u = s * 256 + tid;
            int row = u >> 4, j = u & 15;
            uint32_t h0, h1, h2, h3, l0, l1, l2, l3;
            split2h(p0.x, p0.y, h0, l0);
            split2h(p0.z, p0.w, h1, l1);
            split2h(p1.x, p1.y, h2, l2);
            split2h(p1.z, p1.w, h3, l3);
            int off = row * 256 + ((j ^ (row & 7)) << 4);
            *(uint4*)(smc + A1HI_B + off) = make_uint4(h0, h1, h2, h3);
            *(uint4*)(smc + A1LO_B + off) = make_uint4(l0, l1, l2, l3);
        }
        p0 = n0; p1 = n1;
    }
    CPWAIT(0);          // B1 resident
    __syncthreads();    // + A1 stores visible

    // ===== MMA chunk 1 =====
    #pragma unroll 1
    for (int s = 0; s < 8; ++s) kstep(a1h, a1l, b1, s);
    __syncthreads();    // all reads of A/B done before image overwrite

    // ===== Epilogue: fragments -> fp16 hi/lo Q(K,V) images (Q scaled 1/8) =====
    {
        const int r0 = lid >> 2;
        const int c4 = lid & 3;
        #pragma unroll
        for (int mt = 0; mt < 2; ++mt) {
            #pragma unroll
            for (int nt = 0; nt < 12; ++nt) {
                int n = nbase + 8 * nt;
                int hiB, loB, m;
                float sc;
                if (n < 64)       { hiB = QHI_B; loB = QLO_B; m = n;       sc = 0.125f; }
                else if (n < 128) { hiB = KHI_B; loB = KLO_B; m = n - 64;  sc = 1.f; }
                else              { hiB = VHI_B; loB = VLO_B; m = n - 128; sc = 1.f; }
                int u   = m >> 3;
                int row = mbase + mt * 16 + r0;
                uint32_t h0, l0, h1, l1;
                split2h(sc * acc[mt][nt][0], sc * acc[mt][nt][1], h0, l0);
                split2h(sc * acc[mt][nt][2], sc * acc[mt][nt][3], h1, l1);
                int byt0 = row * 128 + ((u ^ (row & 7)) << 4) + c4 * 4;
                int rw8  = row + 8;
                int byt1 = rw8 * 128 + ((u ^ (rw8 & 7)) << 4) + c4 * 4;
                *(uint32_t*)(smc + hiB + byt0) = h0;
                *(uint32_t*)(smc + loB + byt0) = l0;
                *(uint32_t*)(smc + hiB + byt1) = h1;
                *(uint32_t*)(smc + loB + byt1) = l1;
            }
        }
    }
    __syncthreads();

    // ===== Phase 2: tensor-core attention (3-term fp16) =====
    const int rw    = wid * 16;
    const int rofsA = (lid & 7) + ((lid >> 3) & 1) * 8;
    const int jselA = (lid >> 4) & 1;
    const int rofsK = (lid & 7) + ((lid >> 4) & 1) * 8;
    const int jselK = (lid >> 3) & 1;
    const int xorr  = lid & 7;
    const int vub   = (lid >> 4) & 1;

    uint32_t qh[4][4], ql[4][4];
    #pragma unroll
    for (int s = 0; s < 4; ++s) {
        uint32_t off = (uint32_t)((rw + rofsA) * 128 + (((2 * s + jselA) ^ xorr) << 4));
        ldsm4(qh[s], sb + QHI_B + off);
        ldsm4(ql[s], sb + QLO_B + off);
    }

    float sacc[16][4];
    #pragma unroll
    for (int nb = 0; nb < 16; ++nb)
        #pragma unroll
        for (int i = 0; i < 4; ++i) sacc[nb][i] = 0.f;

    #pragma unroll
    for (int pb = 0; pb < 8; ++pb) {
        if (pb <= wid) {
            #pragma unroll
            for (int s = 0; s < 4; ++s) {
                uint32_t off = (uint32_t)((16 * pb + rofsK) * 128 +
                                          (((2 * s + jselK) ^ xorr) << 4));
                uint32_t kh[4], kl[4];
                ldsm4(kh, sb + KHI_B + off);
                ldsm4(kl, sb + KLO_B + off);
                #pragma unroll
                for (int nn = 0; nn < 2; ++nn) {
                    float* d = sacc[2 * pb + nn];
                    mma16816(d, qh[s], kh[2 * nn], kh[2 * nn + 1]);
                    mma16816(d, qh[s], kl[2 * nn], kl[2 * nn + 1]);
                    mma16816(d, ql[s], kh[2 * nn], kh[2 * nn + 1]);
                }
            }
        }
    }

    const int r0 = lid >> 2;
    const int cq = (lid & 3) * 2;
    const int rowh = rw + r0;
    const int rowl = rowh + 8;

    float m0 = -1e30f, m1 = -1e30f;
    #pragma unroll
    for (int nb = 0; nb < 16; ++nb) {
        if (nb <= 2 * wid + 1) {
            if (nb >= 2 * wid) {
                int colb = 8 * nb + cq;
                if (colb     > rowh) sacc[nb][0] = -1e30f;
                if (colb + 1 > rowh) sacc[nb][1] = -1e30f;
                if (colb     > rowl) sacc[nb][2] = -1e30f;
                if (colb + 1 > rowl) sacc[nb][3] = -1e30f;
            }
            m0 = fmaxf(m0, fmaxf(sacc[nb][0], sacc[nb][1]));
            m1 = fmaxf(m1, fmaxf(sacc[nb][2], sacc[nb][3]));
        }
    }
    m0 = fmaxf(m0, __shfl_xor_sync(0xffffffffu, m0, 1));
    m0 = fmaxf(m0, __shfl_xor_sync(0xffffffffu, m0, 2));
    m1 = fmaxf(m1, __shfl_xor_sync(0xffffffffu, m1, 1));
    m1 = fmaxf(m1, __shfl_xor_sync(0xffffffffu, m1, 2));

    float s0 = 0.f, s1 = 0.f;
    #pragma unroll
    for (int nb = 0; nb < 16; ++nb) {
        if (nb <= 2 * wid + 1) {
            sacc[nb][0] = __expf(sacc[nb][0] - m0);
            sacc[nb][1] = __expf(sacc[nb][1] - m0);
            sacc[nb][2] = __expf(sacc[nb][2] - m1);
            sacc[nb][3] = __expf(sacc[nb][3] - m1);
            s0 += sacc[nb][0] + sacc[nb][1];
            s1 += sacc[nb][2] + sacc[nb][3];
        }
    }
    s0 += __shfl_xor_sync(0xffffffffu, s0, 1);
    s0 += __shfl_xor_sync(0xffffffffu, s0, 2);
    s1 += __shfl_xor_sync(0xffffffffu, s1, 1);
    s1 += __shfl_xor_sync(0xffffffffu, s1, 2);
    const float inv0 = 1.f / s0;
    const float inv1 = 1.f / s1;

    uint32_t ph[8][4], pl[8][4];
    #pragma unroll
    for (int t = 0; t < 8; ++t) {
        if (t <= wid) {
            split2h(sacc[2 * t][0],     sacc[2 * t][1],     ph[t][0], pl[t][0]);
            split2h(sacc[2 * t][2],     sacc[2 * t][3],     ph[t][1], pl[t][1]);
            split2h(sacc[2 * t + 1][0], sacc[2 * t + 1][1], ph[t][2], pl[t][2]);
            split2h(sacc[2 * t + 1][2], sacc[2 * t + 1][3], ph[t][3], pl[t][3]);
        }
    }

    float oacc[8][4];
    #pragma unroll
    for (int nb = 0; nb < 8; ++nb)
        #pragma unroll
        for (int i = 0; i < 4; ++i) oacc[nb][i] = 0.f;

    #pragma unroll
    for (int t = 0; t < 8; ++t) {
        if (t <= wid) {
            #pragma unroll
            for (int pb = 0; pb < 4; ++pb) {
                uint32_t off = (uint32_t)((16 * t + rofsA) * 128 +
                                          (((2 * pb + vub) ^ xorr) << 4));
                uint32_t vh[4], vl[4];
                ldsm4t(vh, sb + VHI_B + off);
                ldsm4t(vl, sb + VLO_B + off);
                #pragma unroll
                for (int nn = 0; nn < 2; ++nn) {
                    float* d = oacc[2 * pb + nn];
                    mma16816(d, ph[t], vh[2 * nn], vh[2 * nn + 1]);
                    mma16816(d, ph[t], vl[2 * nn], vl[2 * nn + 1]);
                    mma16816(d, pl[t], vh[2 * nn], vh[2 * nn + 1]);
                }
            }
        }
    }

    float* ob = out + (size_t)b * T * H;
    #pragma unroll
    for (int nb = 0; nb < 8; ++nb) {
        int col = 8 * nb + cq;
        float2 v0; v0.x = oacc[nb][0] * inv0; v0.y = oacc[nb][1] * inv0;
        float2 v1; v1.x = oacc[nb][2] * inv1; v1.y = oacc[nb][3] * inv1;
        *(float2*)(ob + rowh * H + col) = v0;
        *(float2*)(ob + rowl * H + col) = v1;
    }
}

// ---------------------------------------------------------------------------
extern "C" void kernel_launch(void* const* d_in, const int* in_sizes, int n_in,
                              void* d_out, int out_size)
{
    using namespace cfg;
    const float* x  = (const float*)d_in[0];
    const float* Wq = (const float*)d_in[1];
    const float* Wk = (const float*)d_in[2];
    const float* Wv = (const float*)d_in[3];
    float* out = (float*)d_out;

    const int B = in_sizes[0] / (T * E);

    build_w_images<<<24, 256>>>(Wq, Wk, Wv);

    cudaFuncSetAttribute(attn_head_kernel,
                         cudaFuncAttributeMaxDynamicSharedMemorySize, SMEM_BYTES);
    attn_head_kernel<<<B, 256, SMEM_BYTES>>>(x, out);
}

// round 11
// speedup vs baseline: 3.3890x; 1.0250x over previous
#include <cuda_runtime.h>
#include <cstdint>
#include <cstddef>

namespace cfg {
constexpr int T  = 128;
constexpr int E  = 256;
constexpr int H  = 64;

// GEMM smem (bytes). A rows: 256B = 128 fp16 (one 128-k chunk), 16B units
// xor-swizzled by (row&7). B rows likewise (192 rows, hi only).
constexpr int A0HI_B = 0;        // 32 KB
constexpr int A0LO_B = 32768;    // 32 KB
constexpr int A1HI_B = 65536;    // 32 KB
constexpr int A1LO_B = 98304;    // 32 KB
constexpr int B0HI_B = 131072;   // 48 KB
constexpr int B1HI_B = 180224;   // 48 KB -> 229376
constexpr int SMEM_BYTES = 229376;

// Attention images overlay A region post-GEMM: [128 rows][64 fp16 = 128B],
// 16B units xor-swizzled by (row&7). K/V are hi-only (2-term attention).
constexpr int QHI_B = 0;
constexpr int QLO_B = 16384;
constexpr int KHI_B = 32768;
constexpr int VHI_B = 49152;     // ends 65536
}

// W^T fp16 (hi only) swizzled images: [chunk(2)][row n(192)][256B]
__device__ __align__(16) unsigned char g_Wh[2 * 49152];

// ---------------------------------------------------------------------------
static __device__ __forceinline__ uint32_t smem_u32(const void* p) {
    uint32_t a;
    asm("{ .reg .u64 t; cvta.to.shared.u64 t, %1; cvt.u32.u64 %0, t; }" : "=r"(a) : "l"(p));
    return a;
}
static __device__ __forceinline__ uint32_t pkh(float f0, float f1) {
    uint32_t r;  // lower half = f16(f0), upper = f16(f1)
    asm("cvt.rn.f16x2.f32 %0, %1, %2;" : "=r"(r) : "f"(f1), "f"(f0));
    return r;
}
static __device__ __forceinline__ void split2h(float f0, float f1, uint32_t& h, uint32_t& l) {
    h = pkh(f0, f1);
    float g0, g1;
    asm("{.reg .b16 a,b;\n\t mov.b32 {a,b}, %2;\n\t cvt.f32.f16 %0, a;\n\t cvt.f32.f16 %1, b;}"
        : "=f"(g0), "=f"(g1) : "r"(h));
    l = pkh(f0 - g0, f1 - g1);
}
static __device__ __forceinline__ void ldsm4(uint32_t r[4], uint32_t addr) {
    asm volatile("ldmatrix.sync.aligned.m8n8.x4.shared.b16 {%0,%1,%2,%3}, [%4];"
                 : "=r"(r[0]), "=r"(r[1]), "=r"(r[2]), "=r"(r[3]) : "r"(addr));
}
static __device__ __forceinline__ void ldsm4t(uint32_t r[4], uint32_t addr) {
    asm volatile("ldmatrix.sync.aligned.m8n8.x4.trans.shared.b16 {%0,%1,%2,%3}, [%4];"
                 : "=r"(r[0]), "=r"(r[1]), "=r"(r[2]), "=r"(r[3]) : "r"(addr));
}
static __device__ __forceinline__ void mma16816(float d[4],
                                                const uint32_t a[4],
                                                uint32_t b0, uint32_t b1) {
    asm volatile(
        "mma.sync.aligned.m16n8k16.row.col.f32.f16.f16.f32 "
        "{%0,%1,%2,%3}, {%4,%5,%6,%7}, {%8,%9}, {%0,%1,%2,%3};"
        : "+f"(d[0]), "+f"(d[1]), "+f"(d[2]), "+f"(d[3])
        : "r"(a[0]), "r"(a[1]), "r"(a[2]), "r"(a[3]), "r"(b0), "r"(b1));
}
#define CP16(dst, src) \
    asm volatile("cp.async.cg.shared.global [%0], [%1], 16;" :: "r"(dst), "l"(src) : "memory")
#define CPCOMMIT() asm volatile("cp.async.commit_group;" ::: "memory")
#define CPWAIT(n)  asm volatile("cp.async.wait_group %0;" :: "n"(n) : "memory")

// ---------------------------------------------------------------------------
// Pre-kernel: swizzled fp16 image of W^T ([n][k], k contiguous), hi only.
// ---------------------------------------------------------------------------
__global__ void build_w_images(const float* __restrict__ Wq,
                               const float* __restrict__ Wk,
                               const float* __restrict__ Wv)
{
    int gid = blockIdx.x * blockDim.x + threadIdx.x;   // 0..6143
    int c   = gid / 3072;
    int u   = gid % 3072;
    int n   = u >> 4;
    int j   = u & 15;
    int k0  = c * 128 + j * 8;

    const float* Wsrc = (n < 64) ? (Wq + n) : (n < 128) ? (Wk + n - 64) : (Wv + n - 128);
    float f[8];
    #pragma unroll
    for (int e = 0; e < 8; ++e) f[e] = Wsrc[(size_t)(k0 + e) * cfg::H];

    uint32_t h[4];
    #pragma unroll
    for (int p = 0; p < 4; ++p) h[p] = pkh(f[2 * p], f[2 * p + 1]);

    size_t off = (size_t)c * 49152 + (size_t)n * 256 + (size_t)((j ^ (n & 7)) << 4);
    *(uint4*)(g_Wh + off) = make_uint4(h[0], h[1], h[2], h[3]);
}

// ---------------------------------------------------------------------------
// Main kernel: one CTA per batch. fp16 split tensor pipeline, cp.async W.
// ---------------------------------------------------------------------------
__global__ __launch_bounds__(256, 1)
void attn_head_kernel(const float* __restrict__ x,
                      float* __restrict__ out)
{
    using namespace cfg;
    extern __shared__ __align__(1024) unsigned char smraw[];
    unsigned char* smc = smraw;

    const int tid = threadIdx.x;
    const int wid = tid >> 5;
    const int lid = tid & 31;
    const int b   = blockIdx.x;
    const uint32_t sb = smem_u32(smraw);
    const float* xb = x + (size_t)b * (T * E);

    // ===== Kick off W copies for both chunks (hi only), fully async =====
    #pragma unroll
    for (int i = 0; i < 12; ++i) {
        int u = i * 256 + tid;
        CP16(sb + B0HI_B + u * 16, g_Wh + u * 16);
    }
    CPCOMMIT();
    #pragma unroll
    for (int i = 0; i < 12; ++i) {
        int u = i * 256 + tid;
        CP16(sb + B1HI_B + u * 16, g_Wh + 49152 + u * 16);
    }
    CPCOMMIT();

    // ===== x chunk 0 -> A0 hi/lo =====
    #pragma unroll
    for (int i = 0; i < 8; ++i) {
        int u   = i * 256 + tid;
        int row = u >> 4;
        int j   = u & 15;
        const float4* src = (const float4*)(xb + (size_t)row * E + j * 8);
        float4 fa = src[0], fb = src[1];
        uint32_t h0, h1, h2, h3, l0, l1, l2, l3;
        split2h(fa.x, fa.y, h0, l0);
        split2h(fa.z, fa.w, h1, l1);
        split2h(fb.x, fb.y, h2, l2);
        split2h(fb.z, fb.w, h3, l3);
        int off = row * 256 + ((j ^ (row & 7)) << 4);
        *(uint4*)(smc + A0HI_B + off) = make_uint4(h0, h1, h2, h3);
        *(uint4*)(smc + A0LO_B + off) = make_uint4(l0, l1, l2, l3);
    }
    CPWAIT(1);          // B0 resident
    __syncthreads();

    // ===== Warp-tile constants (M 4 x N 2 tiling; tile 32x96) =====
    const int mbase = (wid >> 1) * 32;
    const int nbase = (wid & 1) * 96;
    const int arow  = mbase + (lid & 7) + ((lid >> 3) & 1) * 8;
    const int axor  = arow & 7;
    const int ajsel = (lid >> 4) & 1;
    const int brow  = nbase + (lid & 7) + ((lid >> 4) & 1) * 8;
    const int bxor  = brow & 7;
    const int bjsel = (lid >> 3) & 1;

    float acc[2][12][4];
    #pragma unroll
    for (int mt = 0; mt < 2; ++mt)
        #pragma unroll
        for (int nt = 0; nt < 12; ++nt)
            #pragma unroll
            for (int r = 0; r < 4; ++r) acc[mt][nt][r] = 0.f;

    // One k16-step of the 2-term GEMM (hh + lh)
    auto kstep = [&](uint32_t aHi, uint32_t aLo, uint32_t bB, int s) {
        const uint32_t aoff = (uint32_t)(((2 * s + ajsel) ^ axor) << 4);
        const uint32_t boff = (uint32_t)(((2 * s + bjsel) ^ bxor) << 4);
        uint32_t ah[2][4], al[2][4];
        ldsm4(ah[0], aHi + aoff);
        ldsm4(al[0], aLo + aoff);
        ldsm4(ah[1], aHi + 16 * 256 + aoff);
        ldsm4(al[1], aLo + 16 * 256 + aoff);
        #pragma unroll
        for (int g = 0; g < 6; ++g) {
            uint32_t bh[4];
            ldsm4(bh, bB + g * 16 * 256 + boff);
            #pragma unroll
            for (int mt = 0; mt < 2; ++mt) {
                #pragma unroll
                for (int nn = 0; nn < 2; ++nn) {
                    float* d = acc[mt][g * 2 + nn];
                    mma16816(d, ah[mt], bh[2 * nn], bh[2 * nn + 1]);
                    mma16816(d, al[mt], bh[2 * nn], bh[2 * nn + 1]);
                }
            }
        }
    };

    const uint32_t a0h = sb + A0HI_B + arow * 256;
    const uint32_t a0l = sb + A0LO_B + arow * 256;
    const uint32_t a1h = sb + A1HI_B + arow * 256;
    const uint32_t a1l = sb + A1LO_B + arow * 256;
    const uint32_t b0  = sb + B0HI_B + brow * 256;
    const uint32_t b1  = sb + B1HI_B + brow * 256;

    // ===== MMA chunk 0, with x chunk-1 software-pipelined in =====
    float4 p0, p1;
    {
        int row = tid >> 4, j = tid & 15;
        const float4* src = (const float4*)(xb + (size_t)row * E + 128 + j * 8);
        p0 = src[0]; p1 = src[1];
    }
    #pragma unroll 1
    for (int s = 0; s < 8; ++s) {
        float4 n0, n1;
        if (s < 7) {
            int u = (s + 1) * 256 + tid;
            int row = u >> 4, j = u & 15;
            const float4* src = (const float4*)(xb + (size_t)row * E + 128 + j * 8);
            n0 = src[0]; n1 = src[1];
        }
        kstep(a0h, a0l, b0, s);
        {
            int u = s * 256 + tid;
            int row = u >> 4, j = u & 15;
            uint32_t h0, h1, h2, h3, l0, l1, l2, l3;
            split2h(p0.x, p0.y, h0, l0);
            split2h(p0.z, p0.w, h1, l1);
            split2h(p1.x, p1.y, h2, l2);
            split2h(p1.z, p1.w, h3, l3);
            int off = row * 256 + ((j ^ (row & 7)) << 4);
            *(uint4*)(smc + A1HI_B + off) = make_uint4(h0, h1, h2, h3);
            *(uint4*)(smc + A1LO_B + off) = make_uint4(l0, l1, l2, l3);
        }
        p0 = n0; p1 = n1;
    }
    CPWAIT(0);          // B1 resident
    __syncthreads();    // + A1 stores visible

    // ===== MMA chunk 1 =====
    #pragma unroll 1
    for (int s = 0; s < 8; ++s) kstep(a1h, a1l, b1, s);
    __syncthreads();    // all reads of A/B done before image overwrite

    // ===== Epilogue: fragments -> fp16 images. Q: hi+lo (scaled 1/8);
    // ===== K,V: hi only (2-term attention drops their lo terms).
    {
        const int r0 = lid >> 2;
        const int c4 = lid & 3;
        #pragma unroll
        for (int mt = 0; mt < 2; ++mt) {
            #pragma unroll
            for (int nt = 0; nt < 12; ++nt) {
                int n = nbase + 8 * nt;
                int row = mbase + mt * 16 + r0;
                int rw8 = row + 8;
                if (n < 64) {
                    int u = n >> 3;
                    uint32_t h0, l0, h1, l1;
                    split2h(0.125f * acc[mt][nt][0], 0.125f * acc[mt][nt][1], h0, l0);
                    split2h(0.125f * acc[mt][nt][2], 0.125f * acc[mt][nt][3], h1, l1);
                    int byt0 = row * 128 + ((u ^ (row & 7)) << 4) + c4 * 4;
                    int byt1 = rw8 * 128 + ((u ^ (rw8 & 7)) << 4) + c4 * 4;
                    *(uint32_t*)(smc + QHI_B + byt0) = h0;
                    *(uint32_t*)(smc + QLO_B + byt0) = l0;
                    *(uint32_t*)(smc + QHI_B + byt1) = h1;
                    *(uint32_t*)(smc + QLO_B + byt1) = l1;
                } else {
                    int hiB = (n < 128) ? KHI_B : VHI_B;
                    int m   = (n < 128) ? n - 64 : n - 128;
                    int u   = m >> 3;
                    uint32_t h0 = pkh(acc[mt][nt][0], acc[mt][nt][1]);
                    uint32_t h1 = pkh(acc[mt][nt][2], acc[mt][nt][3]);
                    int byt0 = row * 128 + ((u ^ (row & 7)) << 4) + c4 * 4;
                    int byt1 = rw8 * 128 + ((u ^ (rw8 & 7)) << 4) + c4 * 4;
                    *(uint32_t*)(smc + hiB + byt0) = h0;
                    *(uint32_t*)(smc + hiB + byt1) = h1;
                }
            }
        }
    }
    __syncthreads();

    // ===== Phase 2: tensor-core attention (2-term fp16, SMSP-balanced) =====
    // Stripe permutation pairs (0,7),(1,6),(2,5),(3,4) on each SMSP so every
    // SMSP carries 9 causal stripe-blocks instead of up to 12.
    const int qs = (wid < 4) ? wid : 11 - wid;
    const int rw = qs * 16;
    const int rofsA = (lid & 7) + ((lid >> 3) & 1) * 8;
    const int jselA = (lid >> 4) & 1;
    const int rofsK = (lid & 7) + ((lid >> 4) & 1) * 8;
    const int jselK = (lid >> 3) & 1;
    const int xorr  = lid & 7;
    const int vub   = (lid >> 4) & 1;

    uint32_t qh[4][4], ql[4][4];
    #pragma unroll
    for (int s = 0; s < 4; ++s) {
        uint32_t off = (uint32_t)((rw + rofsA) * 128 + (((2 * s + jselA) ^ xorr) << 4));
        ldsm4(qh[s], sb + QHI_B + off);
        ldsm4(ql[s], sb + QLO_B + off);
    }

    float sacc[16][4];
    #pragma unroll
    for (int nb = 0; nb < 16; ++nb)
        #pragma unroll
        for (int i = 0; i < 4; ++i) sacc[nb][i] = 0.f;

    #pragma unroll
    for (int pb = 0; pb < 8; ++pb) {
        if (pb <= qs) {
            #pragma unroll
            for (int s = 0; s < 4; ++s) {
                uint32_t off = (uint32_t)((16 * pb + rofsK) * 128 +
                                          (((2 * s + jselK) ^ xorr) << 4));
                uint32_t kh[4];
                ldsm4(kh, sb + KHI_B + off);
                #pragma unroll
                for (int nn = 0; nn < 2; ++nn) {
                    float* d = sacc[2 * pb + nn];
                    mma16816(d, qh[s], kh[2 * nn], kh[2 * nn + 1]);
                    mma16816(d, ql[s], kh[2 * nn], kh[2 * nn + 1]);
                }
            }
        }
    }

    const int r0 = lid >> 2;
    const int cq = (lid & 3) * 2;
    const int rowh = rw + r0;
    const int rowl = rowh + 8;

    float m0 = -1e30f, m1 = -1e30f;
    #pragma unroll
    for (int nb = 0; nb < 16; ++nb) {
        if (nb <= 2 * qs + 1) {
            if (nb >= 2 * qs) {
                int colb = 8 * nb + cq;
                if (colb     > rowh) sacc[nb][0] = -1e30f;
                if (colb + 1 > rowh) sacc[nb][1] = -1e30f;
                if (colb     > rowl) sacc[nb][2] = -1e30f;
                if (colb + 1 > rowl) sacc[nb][3] = -1e30f;
            }
            m0 = fmaxf(m0, fmaxf(sacc[nb][0], sacc[nb][1]));
            m1 = fmaxf(m1, fmaxf(sacc[nb][2], sacc[nb][3]));
        }
    }
    m0 = fmaxf(m0, __shfl_xor_sync(0xffffffffu, m0, 1));
    m0 = fmaxf(m0, __shfl_xor_sync(0xffffffffu, m0, 2));
    m1 = fmaxf(m1, __shfl_xor_sync(0xffffffffu, m1, 1));
    m1 = fmaxf(m1, __shfl_xor_sync(0xffffffffu, m1, 2));

    float s0 = 0.f, s1 = 0.f;
    #pragma unroll
    for (int nb = 0; nb < 16; ++nb) {
        if (nb <= 2 * qs + 1) {
            sacc[nb][0] = __expf(sacc[nb][0] - m0);
            sacc[nb][1] = __expf(sacc[nb][1] - m0);
            sacc[nb][2] = __expf(sacc[nb][2] - m1);
            sacc[nb][3] = __expf(sacc[nb][3] - m1);
            s0 += sacc[nb][0] + sacc[nb][1];
            s1 += sacc[nb][2] + sacc[nb][3];
        }
    }
    s0 += __shfl_xor_sync(0xffffffffu, s0, 1);
    s0 += __shfl_xor_sync(0xffffffffu, s0, 2);
    s1 += __shfl_xor_sync(0xffffffffu, s1, 1);
    s1 += __shfl_xor_sync(0xffffffffu, s1, 2);
    const float inv0 = 1.f / s0;
    const float inv1 = 1.f / s1;

    // P fragments (split fp16) straight from S accumulators
    uint32_t ph[8][4], pl[8][4];
    #pragma unroll
    for (int t = 0; t < 8; ++t) {
        if (t <= qs) {
            split2h(sacc[2 * t][0],     sacc[2 * t][1],     ph[t][0], pl[t][0]);
            split2h(sacc[2 * t][2],     sacc[2 * t][3],     ph[t][1], pl[t][1]);
            split2h(sacc[2 * t + 1][0], sacc[2 * t + 1][1], ph[t][2], pl[t][2]);
            split2h(sacc[2 * t + 1][2], sacc[2 * t + 1][3], ph[t][3], pl[t][3]);
        }
    }

    float oacc[8][4];
    #pragma unroll
    for (int nb = 0; nb < 8; ++nb)
        #pragma unroll
        for (int i = 0; i < 4; ++i) oacc[nb][i] = 0.f;

    #pragma unroll
    for (int t = 0; t < 8; ++t) {
        if (t <= qs) {
            #pragma unroll
            for (int pb = 0; pb < 4; ++pb) {
                uint32_t off = (uint32_t)((16 * t + rofsA) * 128 +
                                          (((2 * pb + vub) ^ xorr) << 4));
                uint32_t vh[4];
                ldsm4t(vh, sb + VHI_B + off);
                #pragma unroll
                for (int nn = 0; nn < 2; ++nn) {
                    float* d = oacc[2 * pb + nn];
                    mma16816(d, ph[t], vh[2 * nn], vh[2 * nn + 1]);
                    mma16816(d, pl[t], vh[2 * nn], vh[2 * nn + 1]);
                }
            }
        }
    }

    float* ob = out + (size_t)b * T * H;
    #pragma unroll
    for (int nb = 0; nb < 8; ++nb) {
        int col = 8 * nb + cq;
        float2 v0; v0.x = oacc[nb][0] * inv0; v0.y = oacc[nb][1] * inv0;
        float2 v1; v1.x = oacc[nb][2] * inv1; v1.y = oacc[nb][3] * inv1;
        *(float2*)(ob + rowh * H + col) = v0;
        *(float2*)(ob + rowl * H + col) = v1;
    }
}

// ---------------------------------------------------------------------------
extern "C" void kernel_launch(void* const* d_in, const int* in_sizes, int n_in,
                              void* d_out, int out_size)
{
    using namespace cfg;
    const float* x  = (const float*)d_in[0];
    const float* Wq = (const float*)d_in[1];
    const float* Wk = (const float*)d_in[2];
    const float* Wv = (const float*)d_in[3];
    float* out = (float*)d_out;

    const int B = in_sizes[0] / (T * E);

    build_w_images<<<24, 256>>>(Wq, Wk, Wv);

    cudaFuncSetAttribute(attn_head_kernel,
                         cudaFuncAttributeMaxDynamicSharedMemorySize, SMEM_BYTES);
    attn_head_kernel<<<B, 256, SMEM_BYTES>>>(x, out);
}

// round 12
// speedup vs baseline: 3.7986x; 1.1209x over previous
#include <cuda_runtime.h>
#include <cstdint>
#include <cstddef>

namespace cfg {
constexpr int T  = 128;
constexpr int E  = 256;
constexpr int H  = 64;

// GEMM smem (bytes). A rows: 256B = 128 fp16 (one 128-k chunk), 16B units
// xor-swizzled by (row&7). B rows likewise (192 rows, hi only).
constexpr int A0HI_B = 0;        // 32 KB
constexpr int A0LO_B = 32768;    // 32 KB
constexpr int A1HI_B = 65536;    // 32 KB
constexpr int A1LO_B = 98304;    // 32 KB
constexpr int B0HI_B = 131072;   // 48 KB
constexpr int B1HI_B = 180224;   // 48 KB -> 229376
constexpr int SMEM_BYTES = 229376;

// Attention images overlay A region post-GEMM: [128 rows][64 fp16 = 128B],
// 16B units xor-swizzled by (row&7). K/V hi-only (2-term attention).
constexpr int QHI_B = 0;
constexpr int QLO_B = 16384;
constexpr int KHI_B = 32768;
constexpr int VHI_B = 49152;     // ends 65536

// Pair-exchange scratch (overlays dead A1 region post-GEMM).
constexpr int REDM_B  = 65536;   // 2 x 128 fp32 row maxima
constexpr int REDS_B  = 66560;   // 2 x 128 fp32 row sums
constexpr int OPART_B = 67584;   // 128 x OP_STRIDE fp32 partial O
constexpr int OP_STRIDE = 68;    // floats (even: float2-aligned; bank shift 4)
}

// W^T fp16 (hi only) swizzled images: [chunk(2)][row n(192)][256B]
__device__ __align__(16) unsigned char g_Wh[2 * 49152];

// ---------------------------------------------------------------------------
static __device__ __forceinline__ uint32_t smem_u32(const void* p) {
    uint32_t a;
    asm("{ .reg .u64 t; cvta.to.shared.u64 t, %1; cvt.u32.u64 %0, t; }" : "=r"(a) : "l"(p));
    return a;
}
static __device__ __forceinline__ uint32_t pkh(float f0, float f1) {
    uint32_t r;  // lower half = f16(f0), upper = f16(f1)
    asm("cvt.rn.f16x2.f32 %0, %1, %2;" : "=r"(r) : "f"(f1), "f"(f0));
    return r;
}
static __device__ __forceinline__ void split2h(float f0, float f1, uint32_t& h, uint32_t& l) {
    h = pkh(f0, f1);
    float g0, g1;
    asm("{.reg .b16 a,b;\n\t mov.b32 {a,b}, %2;\n\t cvt.f32.f16 %0, a;\n\t cvt.f32.f16 %1, b;}"
        : "=f"(g0), "=f"(g1) : "r"(h));
    l = pkh(f0 - g0, f1 - g1);
}
static __device__ __forceinline__ void ldsm4(uint32_t r[4], uint32_t addr) {
    asm volatile("ldmatrix.sync.aligned.m8n8.x4.shared.b16 {%0,%1,%2,%3}, [%4];"
                 : "=r"(r[0]), "=r"(r[1]), "=r"(r[2]), "=r"(r[3]) : "r"(addr));
}
static __device__ __forceinline__ void ldsm4t(uint32_t r[4], uint32_t addr) {
    asm volatile("ldmatrix.sync.aligned.m8n8.x4.trans.shared.b16 {%0,%1,%2,%3}, [%4];"
                 : "=r"(r[0]), "=r"(r[1]), "=r"(r[2]), "=r"(r[3]) : "r"(addr));
}
static __device__ __forceinline__ void mma16816(float d[4],
                                                const uint32_t a[4],
                                                uint32_t b0, uint32_t b1) {
    asm volatile(
        "mma.sync.aligned.m16n8k16.row.col.f32.f16.f16.f32 "
        "{%0,%1,%2,%3}, {%4,%5,%6,%7}, {%8,%9}, {%0,%1,%2,%3};"
        : "+f"(d[0]), "+f"(d[1]), "+f"(d[2]), "+f"(d[3])
        : "r"(a[0]), "r"(a[1]), "r"(a[2]), "r"(a[3]), "r"(b0), "r"(b1));
}
#define CP16(dst, src) \
    asm volatile("cp.async.cg.shared.global [%0], [%1], 16;" :: "r"(dst), "l"(src) : "memory")
#define CPCOMMIT() asm volatile("cp.async.commit_group;" ::: "memory")
#define CPWAIT(n)  asm volatile("cp.async.wait_group %0;" :: "n"(n) : "memory")

// ---------------------------------------------------------------------------
// Pre-kernel: swizzled fp16 image of W^T ([n][k], k contiguous), hi only.
// ---------------------------------------------------------------------------
__global__ void build_w_images(const float* __restrict__ Wq,
                               const float* __restrict__ Wk,
                               const float* __restrict__ Wv)
{
    int gid = blockIdx.x * blockDim.x + threadIdx.x;   // 0..6143
    int c   = gid / 3072;
    int u   = gid % 3072;
    int n   = u >> 4;
    int j   = u & 15;
    int k0  = c * 128 + j * 8;

    const float* Wsrc = (n < 64) ? (Wq + n) : (n < 128) ? (Wk + n - 64) : (Wv + n - 128);
    float f[8];
    #pragma unroll
    for (int e = 0; e < 8; ++e) f[e] = Wsrc[(size_t)(k0 + e) * cfg::H];

    uint32_t h[4];
    #pragma unroll
    for (int p = 0; p < 4; ++p) h[p] = pkh(f[2 * p], f[2 * p + 1]);

    size_t off = (size_t)c * 49152 + (size_t)n * 256 + (size_t)((j ^ (n & 7)) << 4);
    *(uint4*)(g_Wh + off) = make_uint4(h[0], h[1], h[2], h[3]);
}

// ---------------------------------------------------------------------------
// Main kernel: one CTA (512 threads) per batch.
// ---------------------------------------------------------------------------
__global__ __launch_bounds__(512, 1)
void attn_head_kernel(const float* __restrict__ x,
                      float* __restrict__ out)
{
    using namespace cfg;
    extern __shared__ __align__(1024) unsigned char smraw[];
    unsigned char* smc = smraw;
    float*         smp = (float*)smraw;

    const int tid = threadIdx.x;
    const int wid = tid >> 5;
    const int lid = tid & 31;
    const int b   = blockIdx.x;
    const uint32_t sb = smem_u32(smraw);
    const float* xb = x + (size_t)b * (T * E);

    // ===== Kick off W copies for both chunks (hi only), fully async =====
    #pragma unroll
    for (int i = 0; i < 6; ++i) {
        int u = i * 512 + tid;
        CP16(sb + B0HI_B + u * 16, g_Wh + u * 16);
    }
    CPCOMMIT();
    #pragma unroll
    for (int i = 0; i < 6; ++i) {
        int u = i * 512 + tid;
        CP16(sb + B1HI_B + u * 16, g_Wh + 49152 + u * 16);
    }
    CPCOMMIT();

    // ===== x chunk 0 -> A0 hi/lo =====
    #pragma unroll
    for (int i = 0; i < 4; ++i) {
        int u   = i * 512 + tid;
        int row = u >> 4;
        int j   = u & 15;
        const float4* src = (const float4*)(xb + (size_t)row * E + j * 8);
        float4 fa = src[0], fb = src[1];
        uint32_t h0, h1, h2, h3, l0, l1, l2, l3;
        split2h(fa.x, fa.y, h0, l0);
        split2h(fa.z, fa.w, h1, l1);
        split2h(fb.x, fb.y, h2, l2);
        split2h(fb.z, fb.w, h3, l3);
        int off = row * 256 + ((j ^ (row & 7)) << 4);
        *(uint4*)(smc + A0HI_B + off) = make_uint4(h0, h1, h2, h3);
        *(uint4*)(smc + A0LO_B + off) = make_uint4(l0, l1, l2, l3);
    }
    CPWAIT(1);          // B0 resident
    __syncthreads();

    // ===== Warp-tile constants: 4x4 grid, tile 32x48 =====
    const int mbase = (wid >> 2) * 32;
    const int nbase = (wid & 3) * 48;
    const int arow  = mbase + (lid & 7) + ((lid >> 3) & 1) * 8;
    const int axor  = arow & 7;
    const int ajsel = (lid >> 4) & 1;
    const int brow  = nbase + (lid & 7) + ((lid >> 4) & 1) * 8;
    const int bxor  = brow & 7;
    const int bjsel = (lid >> 3) & 1;

    float acc[2][6][4];
    #pragma unroll
    for (int mt = 0; mt < 2; ++mt)
        #pragma unroll
        for (int nt = 0; nt < 6; ++nt)
            #pragma unroll
            for (int r = 0; r < 4; ++r) acc[mt][nt][r] = 0.f;

    // One k16-step of the 2-term GEMM (hh + lh)
    auto kstep = [&](uint32_t aHi, uint32_t aLo, uint32_t bB, int s) {
        const uint32_t aoff = (uint32_t)(((2 * s + ajsel) ^ axor) << 4);
        const uint32_t boff = (uint32_t)(((2 * s + bjsel) ^ bxor) << 4);
        uint32_t ah[2][4], al[2][4];
        ldsm4(ah[0], aHi + aoff);
        ldsm4(al[0], aLo + aoff);
        ldsm4(ah[1], aHi + 16 * 256 + aoff);
        ldsm4(al[1], aLo + 16 * 256 + aoff);
        #pragma unroll
        for (int g = 0; g < 3; ++g) {
            uint32_t bh[4];
            ldsm4(bh, bB + g * 16 * 256 + boff);
            #pragma unroll
            for (int mt = 0; mt < 2; ++mt) {
                #pragma unroll
                for (int nn = 0; nn < 2; ++nn) {
                    float* d = acc[mt][g * 2 + nn];
                    mma16816(d, ah[mt], bh[2 * nn], bh[2 * nn + 1]);
                    mma16816(d, al[mt], bh[2 * nn], bh[2 * nn + 1]);
                }
            }
        }
    };

    const uint32_t a0h = sb + A0HI_B + arow * 256;
    const uint32_t a0l = sb + A0LO_B + arow * 256;
    const uint32_t a1h = sb + A1HI_B + arow * 256;
    const uint32_t a1l = sb + A1LO_B + arow * 256;
    const uint32_t b0  = sb + B0HI_B + brow * 256;
    const uint32_t b1  = sb + B1HI_B + brow * 256;

    // ===== MMA chunk 0, x chunk-1 convert pipelined on even k-steps =====
    float4 p0, p1;
    {
        int row = tid >> 4, j = tid & 15;
        const float4* src = (const float4*)(xb + (size_t)row * E + 128 + j * 8);
        p0 = src[0]; p1 = src[1];
    }
    #pragma unroll 1
    for (int s = 0; s < 8; ++s) {
        kstep(a0h, a0l, b0, s);
        if ((s & 1) == 0) {
            int i = s >> 1;
            int u = i * 512 + tid;
            int row = u >> 4, j = u & 15;
            uint32_t h0, h1, h2, h3, l0, l1, l2, l3;
            split2h(p0.x, p0.y, h0, l0);
            split2h(p0.z, p0.w, h1, l1);
            split2h(p1.x, p1.y, h2, l2);
            split2h(p1.z, p1.w, h3, l3);
            int off = row * 256 + ((j ^ (row & 7)) << 4);
            *(uint4*)(smc + A1HI_B + off) = make_uint4(h0, h1, h2, h3);
            *(uint4*)(smc + A1LO_B + off) = make_uint4(l0, l1, l2, l3);
            if (i < 3) {
                int u2 = (i + 1) * 512 + tid;
                int r2 = u2 >> 4, j2 = u2 & 15;
                const float4* src = (const float4*)(xb + (size_t)r2 * E + 128 + j2 * 8);
                p0 = src[0]; p1 = src[1];
            }
        }
    }
    CPWAIT(0);          // B1 resident
    __syncthreads();    // + A1 stores visible

    // ===== MMA chunk 1 =====
    #pragma unroll 1
    for (int s = 0; s < 8; ++s) kstep(a1h, a1l, b1, s);
    __syncthreads();    // all reads of A/B done before image overwrite

    // ===== Epilogue: fragments -> fp16 images (Q hi+lo scaled 1/8; K,V hi) =====
    {
        const int r0 = lid >> 2;
        const int c4 = lid & 3;
        #pragma unroll
        for (int mt = 0; mt < 2; ++mt) {
            #pragma unroll
            for (int nt = 0; nt < 6; ++nt) {
                int n = nbase + 8 * nt;
                int row = mbase + mt * 16 + r0;
                int rw8 = row + 8;
                if (n < 64) {
                    int u = n >> 3;
                    uint32_t h0, l0, h1, l1;
                    split2h(0.125f * acc[mt][nt][0], 0.125f * acc[mt][nt][1], h0, l0);
                    split2h(0.125f * acc[mt][nt][2], 0.125f * acc[mt][nt][3], h1, l1);
                    int byt0 = row * 128 + ((u ^ (row & 7)) << 4) + c4 * 4;
                    int byt1 = rw8 * 128 + ((u ^ (rw8 & 7)) << 4) + c4 * 4;
                    *(uint32_t*)(smc + QHI_B + byt0) = h0;
                    *(uint32_t*)(smc + QLO_B + byt0) = l0;
                    *(uint32_t*)(smc + QHI_B + byt1) = h1;
                    *(uint32_t*)(smc + QLO_B + byt1) = l1;
                } else {
                    int hiB = (n < 128) ? KHI_B : VHI_B;
                    int m   = (n < 128) ? n - 64 : n - 128;
                    int u   = m >> 3;
                    uint32_t h0 = pkh(acc[mt][nt][0], acc[mt][nt][1]);
                    uint32_t h1 = pkh(acc[mt][nt][2], acc[mt][nt][3]);
                    int byt0 = row * 128 + ((u ^ (row & 7)) << 4) + c4 * 4;
                    int byt1 = rw8 * 128 + ((u ^ (rw8 & 7)) << 4) + c4 * 4;
                    *(uint32_t*)(smc + hiB + byt0) = h0;
                    *(uint32_t*)(smc + hiB + byt1) = h1;
                }
            }
        }
    }
    __syncthreads();

    // ===== Phase 2: attention. Warp pair (p, mem) shares stripe qs; =====
    // ===== members split causal key-blocks even/odd.                 =====
    const int pr  = wid & 7;
    const int mem = wid >> 3;                       // 0 or 1
    const int qs  = (pr < 4) ? pr : 11 - pr;        // SMSP-balanced stripes
    const int rw  = qs * 16;
    const int rofsA = (lid & 7) + ((lid >> 3) & 1) * 8;
    const int jselA = (lid >> 4) & 1;
    const int rofsK = (lid & 7) + ((lid >> 4) & 1) * 8;
    const int jselK = (lid >> 3) & 1;
    const int xorr  = lid & 7;
    const int vub   = (lid >> 4) & 1;

    uint32_t qh[4][4], ql[4][4];
    #pragma unroll
    for (int s = 0; s < 4; ++s) {
        uint32_t off = (uint32_t)((rw + rofsA) * 128 + (((2 * s + jselA) ^ xorr) << 4));
        ldsm4(qh[s], sb + QHI_B + off);
        ldsm4(ql[s], sb + QLO_B + off);
    }

    // S blocks for key-blocks pb = mem, mem+2, ... (<= qs)
    float sacc[4][2][4];
    #pragma unroll
    for (int it = 0; it < 4; ++it)
        #pragma unroll
        for (int nn = 0; nn < 2; ++nn)
            #pragma unroll
            for (int i = 0; i < 4; ++i) sacc[it][nn][i] = 0.f;

    #pragma unroll
    for (int it = 0; it < 4; ++it) {
        int pb = 2 * it + mem;
        if (pb <= qs) {
            #pragma unroll
            for (int s = 0; s < 4; ++s) {
                uint32_t off = (uint32_t)((16 * pb + rofsK) * 128 +
                                          (((2 * s + jselK) ^ xorr) << 4));
                uint32_t kh[4];
                ldsm4(kh, sb + KHI_B + off);
                #pragma unroll
                for (int nn = 0; nn < 2; ++nn) {
                    float* d = sacc[it][nn];
                    mma16816(d, qh[s], kh[2 * nn], kh[2 * nn + 1]);
                    mma16816(d, ql[s], kh[2 * nn], kh[2 * nn + 1]);
                }
            }
        }
    }

    const int r0   = lid >> 2;
    const int cq   = (lid & 3) * 2;
    const int rowh = rw + r0;
    const int rowl = rowh + 8;
    float* redm = smp + (REDM_B >> 2);
    float* reds = smp + (REDS_B >> 2);
    float* opar = smp + (OPART_B >> 2);

    // Mask diagonal block + local row max
    float m0 = -1e30f, m1 = -1e30f;
    #pragma unroll
    for (int it = 0; it < 4; ++it) {
        int pb = 2 * it + mem;
        if (pb <= qs) {
            #pragma unroll
            for (int nn = 0; nn < 2; ++nn) {
                if (pb == qs) {
                    int colb = 16 * pb + 8 * nn + cq;
                    if (colb     > rowh) sacc[it][nn][0] = -1e30f;
                    if (colb + 1 > rowh) sacc[it][nn][1] = -1e30f;
                    if (colb     > rowl) sacc[it][nn][2] = -1e30f;
                    if (colb + 1 > rowl) sacc[it][nn][3] = -1e30f;
                }
                m0 = fmaxf(m0, fmaxf(sacc[it][nn][0], sacc[it][nn][1]));
                m1 = fmaxf(m1, fmaxf(sacc[it][nn][2], sacc[it][nn][3]));
            }
        }
    }
    m0 = fmaxf(m0, __shfl_xor_sync(0xffffffffu, m0, 1));
    m0 = fmaxf(m0, __shfl_xor_sync(0xffffffffu, m0, 2));
    m1 = fmaxf(m1, __shfl_xor_sync(0xffffffffu, m1, 1));
    m1 = fmaxf(m1, __shfl_xor_sync(0xffffffffu, m1, 2));
    if ((lid & 3) == 0) {
        redm[mem * 128 + rowh] = m0;
        redm[mem * 128 + rowl] = m1;
    }
    __syncthreads();
    const float mx0 = fmaxf(redm[rowh], redm[128 + rowh]);
    const float mx1 = fmaxf(redm[rowl], redm[128 + rowl]);

    float s0 = 0.f, s1 = 0.f;
    #pragma unroll
    for (int it = 0; it < 4; ++it) {
        int pb = 2 * it + mem;
        if (pb <= qs) {
            #pragma unroll
            for (int nn = 0; nn < 2; ++nn) {
                sacc[it][nn][0] = __expf(sacc[it][nn][0] - mx0);
                sacc[it][nn][1] = __expf(sacc[it][nn][1] - mx0);
                sacc[it][nn][2] = __expf(sacc[it][nn][2] - mx1);
                sacc[it][nn][3] = __expf(sacc[it][nn][3] - mx1);
                s0 += sacc[it][nn][0] + sacc[it][nn][1];
                s1 += sacc[it][nn][2] + sacc[it][nn][3];
            }
        }
    }
    s0 += __shfl_xor_sync(0xffffffffu, s0, 1);
    s0 += __shfl_xor_sync(0xffffffffu, s0, 2);
    s1 += __shfl_xor_sync(0xffffffffu, s1, 1);
    s1 += __shfl_xor_sync(0xffffffffu, s1, 2);
    if ((lid & 3) == 0) {
        reds[mem * 128 + rowh] = s0;
        reds[mem * 128 + rowl] = s1;
    }

    // P fragments (split fp16) from S accumulators
    uint32_t ph[4][4], pl[4][4];
    #pragma unroll
    for (int it = 0; it < 4; ++it) {
        int pb = 2 * it + mem;
        if (pb <= qs) {
            split2h(sacc[it][0][0], sacc[it][0][1], ph[it][0], pl[it][0]);
            split2h(sacc[it][0][2], sacc[it][0][3], ph[it][1], pl[it][1]);
            split2h(sacc[it][1][0], sacc[it][1][1], ph[it][2], pl[it][2]);
            split2h(sacc[it][1][2], sacc[it][1][3], ph[it][3], pl[it][3]);
        }
    }

    float oacc[8][4];
    #pragma unroll
    for (int nb = 0; nb < 8; ++nb)
        #pragma unroll
        for (int i = 0; i < 4; ++i) oacc[nb][i] = 0.f;

    #pragma unroll
    for (int it = 0; it < 4; ++it) {
        int pb = 2 * it + mem;
        if (pb <= qs) {
            #pragma unroll
            for (int cg = 0; cg < 4; ++cg) {
                uint32_t off = (uint32_t)((16 * pb + rofsA) * 128 +
                                          (((2 * cg + vub) ^ xorr) << 4));
                uint32_t vh[4];
                ldsm4t(vh, sb + VHI_B + off);
                #pragma unroll
                for (int nn = 0; nn < 2; ++nn) {
                    float* d = oacc[2 * cg + nn];
                    mma16816(d, ph[it], vh[2 * nn], vh[2 * nn + 1]);
                    mma16816(d, pl[it], vh[2 * nn], vh[2 * nn + 1]);
                }
            }
        }
    }

    // Member 0 stores partial O; member 1 combines, scales, writes out.
    if (mem == 0) {
        #pragma unroll
        for (int nb = 0; nb < 8; ++nb) {
            int col = 8 * nb + cq;
            float2 v0; v0.x = oacc[nb][0]; v0.y = oacc[nb][1];
            float2 v1; v1.x = oacc[nb][2]; v1.y = oacc[nb][3];
            *(float2*)(opar + rowh * OP_STRIDE + col) = v0;
            *(float2*)(opar + rowl * OP_STRIDE + col) = v1;
        }
    }
    __syncthreads();
    if (mem == 1) {
        const float inv0 = 1.f / (reds[rowh] + reds[128 + rowh]);
        const float inv1 = 1.f / (reds[rowl] + reds[128 + rowl]);
        float* ob = out + (size_t)b * T * H;
        #pragma unroll
        for (int nb = 0; nb < 8; ++nb) {
            int col = 8 * nb + cq;
            float2 u0 = *(float2*)(opar + rowh * OP_STRIDE + col);
            float2 u1 = *(float2*)(opar + rowl * OP_STRIDE + col);
            float2 v0; v0.x = (oacc[nb][0] + u0.x) * inv0; v0.y = (oacc[nb][1] + u0.y) * inv0;
            float2 v1; v1.x = (oacc[nb][2] + u1.x) * inv1; v1.y = (oacc[nb][3] + u1.y) * inv1;
            *(float2*)(ob + rowh * H + col) = v0;
            *(float2*)(ob + rowl * H + col) = v1;
        }
    }
}

// ---------------------------------------------------------------------------
extern "C" void kernel_launch(void* const* d_in, const int* in_sizes, int n_in,
                              void* d_out, int out_size)
{
    using namespace cfg;
    const float* x  = (const float*)d_in[0];
    const float* Wq = (const float*)d_in[1];
    const float* Wk = (const float*)d_in[2];
    const float* Wv = (const float*)d_in[3];
    float* out = (float*)d_out;

    const int B = in_sizes[0] / (T * E);

    build_w_images<<<24, 256>>>(Wq, Wk, Wv);

    cudaFuncSetAttribute(attn_head_kernel,
                         cudaFuncAttributeMaxDynamicSharedMemorySize, SMEM_BYTES);
    attn_head_kernel<<<B, 512, SMEM_BYTES>>>(x, out);
}